// round 6
// baseline (speedup 1.0000x reference)
#include <cuda_runtime.h>
#include <cuda_bf16.h>
#include <math.h>
#include <cstdint>

// ---------------- problem constants ----------------
#define Bb   2
#define Ss   2048
#define HID  2048
#define NHh  16
#define QLORA 1536
#define KVLORA 512
#define NOPE 128
#define ROPED 64
#define VDIM 128
#define QKD  192
#define ROWS (Bb*Ss)          // 4096
#define WKVA_NPAD 640
#define SCALEF 0.07216878364870322f

// ---------------- fp32 scratch ----------------
__device__ float g_qc   [(size_t)ROWS * QLORA];
__device__ float g_q    [(size_t)ROWS * NHh * QKD];
__device__ float g_kvt  [(size_t)ROWS * (KVLORA+ROPED)];

// ---------------- bf16 split scratch (activations) ----------------
__device__ __nv_bfloat16 g_hs_h [(size_t)ROWS*HID],    g_hs_l [(size_t)ROWS*HID];
__device__ __nv_bfloat16 g_qc_h [(size_t)ROWS*QLORA],  g_qc_l [(size_t)ROWS*QLORA];
__device__ __nv_bfloat16 g_kvc_h[(size_t)ROWS*KVLORA], g_kvc_l[(size_t)ROWS*KVLORA];
__device__ __nv_bfloat16 g_at_h [(size_t)ROWS*NHh*VDIM], g_at_l[(size_t)ROWS*NHh*VDIM];

// ---------------- bf16 split scratch (transposed weights, [N,K]) ----------
__device__ __nv_bfloat16 g_wqa_h [(size_t)QLORA*HID],            g_wqa_l [(size_t)QLORA*HID];
__device__ __nv_bfloat16 g_wqb_h [(size_t)(NHh*QKD)*QLORA],      g_wqb_l [(size_t)(NHh*QKD)*QLORA];
__device__ __nv_bfloat16 g_wkva_h[(size_t)WKVA_NPAD*HID],        g_wkva_l[(size_t)WKVA_NPAD*HID];
__device__ __nv_bfloat16 g_wkvb_h[(size_t)(NHh*(NOPE+VDIM))*KVLORA], g_wkvb_l[(size_t)(NHh*(NOPE+VDIM))*KVLORA];
__device__ __nv_bfloat16 g_wo_h  [(size_t)HID*(NHh*VDIM)],       g_wo_l  [(size_t)HID*(NHh*VDIM)];

// ---------------- flash bf16 buffers, [b,h,s,d] contiguous ----------
__device__ __nv_bfloat16 g_qfh[(size_t)ROWS*NHh*QKD], g_qfl[(size_t)ROWS*NHh*QKD];
__device__ __nv_bfloat16 g_kfh[(size_t)ROWS*NHh*QKD], g_kfl[(size_t)ROWS*NHh*QKD];
__device__ __nv_bfloat16 g_vfh[(size_t)ROWS*NHh*VDIM], g_vfl[(size_t)ROWS*NHh*VDIM];

// ================= helpers =================
__device__ __forceinline__ uint32_t smem_u32(const void* p) {
    uint32_t a;
    asm("{ .reg .u64 t; cvta.to.shared.u64 t, %1; cvt.u32.u64 %0, t; }" : "=r"(a) : "l"(p));
    return a;
}

#define LDSM4(r, a) asm volatile( \
    "ldmatrix.sync.aligned.m8n8.x4.shared.b16 {%0,%1,%2,%3}, [%4];" \
    : "=r"((r)[0]),"=r"((r)[1]),"=r"((r)[2]),"=r"((r)[3]) : "r"(a))

#define LDSM4T(r, a) asm volatile( \
    "ldmatrix.sync.aligned.m8n8.x4.trans.shared.b16 {%0,%1,%2,%3}, [%4];" \
    : "=r"((r)[0]),"=r"((r)[1]),"=r"((r)[2]),"=r"((r)[3]) : "r"(a))

#define MMA16816(d, a, b0v, b1v) asm volatile( \
    "mma.sync.aligned.m16n8k16.row.col.f32.bf16.bf16.f32 " \
    "{%0,%1,%2,%3},{%4,%5,%6,%7},{%8,%9},{%0,%1,%2,%3};" \
    : "+f"((d)[0]),"+f"((d)[1]),"+f"((d)[2]),"+f"((d)[3]) \
    : "r"((a)[0]),"r"((a)[1]),"r"((a)[2]),"r"((a)[3]), "r"(b0v),"r"(b1v))

#define CP_ASYNC16(sa, ga) asm volatile( \
    "cp.async.cg.shared.global [%0], [%1], 16;" :: "r"(sa), "l"(ga))
#define CP_COMMIT() asm volatile("cp.async.commit_group;" ::: "memory")
#define CP_WAIT1()  asm volatile("cp.async.wait_group 1;" ::: "memory")
#define CP_WAIT0()  asm volatile("cp.async.wait_group 0;" ::: "memory")

__device__ __forceinline__ void split_hl(float v, __nv_bfloat16& h, __nv_bfloat16& l) {
    h = __float2bfloat16(v);
    l = __float2bfloat16(v - __bfloat162float(h));
}

// ================= bf16x2 HMMA GEMM, 3-stage pipeline (unchanged R5) ========
#define BK 32
#define PITCH 40
#define TILE_B (128*PITCH*2)
#define STAGE_B (4*TILE_B)            // 40960
#define NSTAGE 3
#define GEMM_SMEM (NSTAGE*STAGE_B)    // 122880

template<int MODE>
__global__ void __launch_bounds__(256, 1) mma_gemm_t(
    const __nv_bfloat16* __restrict__ Ah, const __nv_bfloat16* __restrict__ Al,
    const __nv_bfloat16* __restrict__ Bh, const __nv_bfloat16* __restrict__ Bl,
    float* __restrict__ C,
    __nv_bfloat16* __restrict__ P0, __nv_bfloat16* __restrict__ P1,
    __nv_bfloat16* __restrict__ P2, __nv_bfloat16* __restrict__ P3,
    int M, int N, int K) {
    extern __shared__ char sm[];
    uint32_t sbase = smem_u32(sm);

    int tid = threadIdx.x, lane = tid & 31, wid = tid >> 5;
    int warpM = wid & 3, warpN = wid >> 2;
    int row0 = blockIdx.y * 128, col0 = blockIdx.x * 128;

    const __nv_bfloat16* gsrc[4] = {
        Ah + (size_t)row0 * K, Al + (size_t)row0 * K,
        Bh + (size_t)col0 * K, Bl + (size_t)col0 * K };

    auto issue_loads = [&](int c, int s) {
        int k0 = c * BK;
        uint32_t st = sbase + s * STAGE_B;
#pragma unroll
        for (int t = 0; t < 4; t++) {
#pragma unroll
            for (int j = 0; j < 2; j++) {
                int seg = tid + j * 256;
                int r = seg >> 2, cc = seg & 3;
                const __nv_bfloat16* g = gsrc[t] + (size_t)r * K + k0 + cc * 8;
                uint32_t sa = st + t * TILE_B + r * (PITCH * 2) + cc * 16;
                CP_ASYNC16(sa, g);
            }
        }
        CP_COMMIT();
    };

    float acc[2][8][4];
#pragma unroll
    for (int i = 0; i < 2; i++)
#pragma unroll
        for (int j = 0; j < 8; j++)
#pragma unroll
            for (int k = 0; k < 4; k++) acc[i][j][k] = 0.f;

    int a_r = warpM * 32 + (lane & 15);
    int a_c8 = (lane >> 4) << 3;
    int b_r = warpN * 64 + ((lane >> 4) << 3) + (lane & 7);
    int b_c8 = ((lane >> 3) & 1) << 3;

    auto compute = [&](int s) {
        uint32_t st = sbase + s * STAGE_B;
#pragma unroll
        for (int ki = 0; ki < 2; ki++) {
            uint32_t ah[2][4], al[2][4];
#pragma unroll
            for (int mi = 0; mi < 2; mi++) {
                uint32_t off = (uint32_t)((a_r + mi * 16) * (PITCH * 2) + (ki * 16 + a_c8) * 2);
                LDSM4(ah[mi], st + off);
                LDSM4(al[mi], st + TILE_B + off);
            }
            uint32_t bh[4][4], bl[4][4];
#pragma unroll
            for (int nb = 0; nb < 4; nb++) {
                uint32_t off = (uint32_t)((b_r + nb * 16) * (PITCH * 2) + (ki * 16 + b_c8) * 2);
                LDSM4(bh[nb], st + 2 * TILE_B + off);
                LDSM4(bl[nb], st + 3 * TILE_B + off);
            }
#pragma unroll
            for (int mi = 0; mi < 2; mi++)
#pragma unroll
                for (int nb = 0; nb < 4; nb++) {
                    MMA16816(acc[mi][2*nb],   ah[mi], bh[nb][0], bh[nb][1]);
                    MMA16816(acc[mi][2*nb],   ah[mi], bl[nb][0], bl[nb][1]);
                    MMA16816(acc[mi][2*nb],   al[mi], bh[nb][0], bh[nb][1]);
                    MMA16816(acc[mi][2*nb+1], ah[mi], bh[nb][2], bh[nb][3]);
                    MMA16816(acc[mi][2*nb+1], ah[mi], bl[nb][2], bl[nb][3]);
                    MMA16816(acc[mi][2*nb+1], al[mi], bh[nb][2], bh[nb][3]);
                }
        }
    };

    int nc = K / BK;
    issue_loads(0, 0);
    issue_loads(1, 1);
    for (int c = 0; c < nc; c++) {
        int s = c % NSTAGE;
        if (c + 1 < nc) { CP_WAIT1(); } else { CP_WAIT0(); }
        __syncthreads();
        if (c + 2 < nc) issue_loads(c + 2, (c + 2) % NSTAGE);
        compute(s);
    }

    int g = lane >> 2, t = lane & 3;
    if (MODE == 0) {
#pragma unroll
        for (int mi = 0; mi < 2; mi++)
#pragma unroll
            for (int n8 = 0; n8 < 8; n8++) {
                int col = col0 + warpN * 64 + n8 * 8 + t * 2;
                if (col < N) {
                    int r0 = row0 + warpM * 32 + mi * 16 + g;
                    float* p0 = C + (size_t)r0 * N + col;
                    p0[0] = acc[mi][n8][0]; p0[1] = acc[mi][n8][1];
                    float* p1 = p0 + (size_t)8 * N;
                    p1[0] = acc[mi][n8][2]; p1[1] = acc[mi][n8][3];
                }
            }
    } else {
        int hH = col0 >> 8;
        int isV = (col0 >> 7) & 1;
        __nv_bfloat16* Dh = isV ? P2 : P0;
        __nv_bfloat16* Dl = isV ? P3 : P1;
        int stride = isV ? VDIM : QKD;
#pragma unroll
        for (int mi = 0; mi < 2; mi++)
#pragma unroll
            for (int n8 = 0; n8 < 8; n8++) {
                int col = col0 + warpN * 64 + n8 * 8 + t * 2;
                int d = col & 127;
#pragma unroll
                for (int rr = 0; rr < 2; rr++) {
                    int r0 = row0 + warpM * 32 + mi * 16 + g + rr * 8;
                    int b = r0 >> 11, srow = r0 & 2047;
                    size_t o = ((size_t)(b * NHh + hH) * Ss + srow) * stride + d;
                    __nv_bfloat16 h0, l0v, h1, l1v;
                    split_hl(acc[mi][n8][rr*2],   h0, l0v);
                    split_hl(acc[mi][n8][rr*2+1], h1, l1v);
                    *(__nv_bfloat162*)(Dh + o) = __nv_bfloat162(h0, h1);
                    *(__nv_bfloat162*)(Dl + o) = __nv_bfloat162(l0v, l1v);
                }
            }
    }
}

// ================= conversion / transpose kernels =================
__global__ void convert_split(const float* __restrict__ x, __nv_bfloat16* __restrict__ h,
                              __nv_bfloat16* __restrict__ l, size_t n) {
    size_t i = ((size_t)blockIdx.x * 256 + threadIdx.x) * 4;
    if (i >= n) return;
    float4 v = *(const float4*)(x + i);
    float a[4] = {v.x, v.y, v.z, v.w};
    __nv_bfloat16 hh[4], ll[4];
#pragma unroll
    for (int j = 0; j < 4; j++) split_hl(a[j], hh[j], ll[j]);
    *(__nv_bfloat162*)(h + i)     = __nv_bfloat162(hh[0], hh[1]);
    *(__nv_bfloat162*)(h + i + 2) = __nv_bfloat162(hh[2], hh[3]);
    *(__nv_bfloat162*)(l + i)     = __nv_bfloat162(ll[0], ll[1]);
    *(__nv_bfloat162*)(l + i + 2) = __nv_bfloat162(ll[2], ll[3]);
}

__global__ void transpose_split(const float* __restrict__ W, __nv_bfloat16* __restrict__ Th,
                                __nv_bfloat16* __restrict__ Tl, int K, int N) {
    __shared__ float tile[32][33];
    int n0 = blockIdx.x * 32, k0 = blockIdx.y * 32;
    int tx = threadIdx.x, ty = threadIdx.y;
#pragma unroll
    for (int i = 0; i < 4; i++) {
        int k = k0 + ty + i * 8, n = n0 + tx;
        tile[ty + i * 8][tx] = (n < N) ? W[(size_t)k * N + n] : 0.f;
    }
    __syncthreads();
#pragma unroll
    for (int i = 0; i < 4; i++) {
        int n = n0 + ty + i * 8;
        float v = tile[tx][ty + i * 8];
        __nv_bfloat16 h, l;
        split_hl(v, h, l);
        Th[(size_t)n * K + k0 + tx] = h;
        Tl[(size_t)n * K + k0 + tx] = l;
    }
}

// ================= fused rmsnorm -> hi/lo =================
__global__ void rmsnorm_split(const float* __restrict__ x, const float* __restrict__ w,
                              __nv_bfloat16* __restrict__ oh, __nv_bfloat16* __restrict__ ol,
                              int L) {
    __shared__ float red[256];
    int tid = threadIdx.x;
    const float* r = x + (size_t)blockIdx.x * L;
    float ss = 0.f;
    for (int i = tid; i < L; i += 256) { float v = r[i]; ss += v * v; }
    red[tid] = ss; __syncthreads();
    for (int s = 128; s > 0; s >>= 1) { if (tid < s) red[tid] += red[tid + s]; __syncthreads(); }
    float scale = rsqrtf(red[0] / (float)L + 1e-6f);
    for (int i = tid; i < L; i += 256) {
        __nv_bfloat16 h, l;
        split_hl(r[i] * scale * w[i], h, l);
        oh[(size_t)blockIdx.x * L + i] = h;
        ol[(size_t)blockIdx.x * L + i] = l;
    }
}

// ================= fused kv split =================
__global__ void kv_split2(const float* __restrict__ kvt, const float* __restrict__ w,
                          const int* __restrict__ pos,
                          __nv_bfloat16* __restrict__ kvch, __nv_bfloat16* __restrict__ kvcl,
                          __nv_bfloat16* __restrict__ kfh, __nv_bfloat16* __restrict__ kfl) {
    __shared__ float red[256];
    __shared__ float rop[64];
    int tid = threadIdx.x, row = blockIdx.x;
    const float* r = kvt + (size_t)row * (KVLORA + ROPED);
    float ss = 0.f;
    for (int i = tid; i < KVLORA; i += 256) { float v = r[i]; ss += v * v; }
    red[tid] = ss; __syncthreads();
    for (int s = 128; s > 0; s >>= 1) { if (tid < s) red[tid] += red[tid + s]; __syncthreads(); }
    float scale = rsqrtf(red[0] / (float)KVLORA + 1e-6f);
    for (int i = tid; i < KVLORA; i += 256) {
        __nv_bfloat16 h, l;
        split_hl(r[i] * scale * w[i], h, l);
        kvch[(size_t)row * KVLORA + i] = h;
        kvcl[(size_t)row * KVLORA + i] = l;
    }
    if (tid < 32) {
        float p = (float)pos[row];
        float inv_freq = powf(10000.f, -(float)tid / 32.f);
        float ang = p * inv_freq;
        float c = cosf(ang), s = sinf(ang);
        float x1 = r[KVLORA + tid];
        float x2 = r[KVLORA + 32 + tid];
        rop[tid]      = x1 * c - x2 * s;
        rop[tid + 32] = x2 * c + x1 * s;
    }
    __syncthreads();
    int b = row >> 11, srow = row & 2047;
    for (int e = tid; e < NHh * ROPED; e += 256) {
        int h = e >> 6, d = e & 63;
        __nv_bfloat16 hh, ll;
        split_hl(rop[d], hh, ll);
        size_t o = ((size_t)(b * NHh + h) * Ss + srow) * QKD + NOPE + d;
        kfh[o] = hh;
        kfl[o] = ll;
    }
}

// ================= fused rope+scale+prep for Q =================
__global__ void rope_prep_q(const float* __restrict__ q, const int* __restrict__ pos,
                            __nv_bfloat16* __restrict__ qfh, __nv_bfloat16* __restrict__ qfl) {
    int row = blockIdx.x;
    int b = row >> 11, srow = row & 2047;
    float p = (float)pos[row];
    const float* qr = q + (size_t)row * (NHh * QKD);
    for (int e = threadIdx.x; e < NHh * QKD; e += 256) {
        int h = e / QKD, d = e % QKD;
        float v;
        if (d < NOPE) v = qr[e];
        else {
            int i = d - NOPE;
            int j = i & 31;
            float inv_freq = powf(10000.f, -(float)j / 32.f);
            float ang = p * inv_freq;
            float c = cosf(ang), s = sinf(ang);
            float x1 = qr[h * QKD + NOPE + j];
            float x2 = qr[h * QKD + NOPE + 32 + j];
            v = (i < 32) ? (x1 * c - x2 * s) : (x2 * c + x1 * s);
        }
        v *= SCALEF;
        __nv_bfloat16 hh, ll;
        split_hl(v, hh, ll);
        size_t o = ((size_t)(b * NHh + h) * Ss + srow) * QKD + d;
        qfh[o] = hh;
        qfl[o] = ll;
    }
}

// ================= tensor-core flash attention v2 =================
// q-tile 128, kv-tile 32, 256 threads (8 warps x 16 q rows), 2 warps/SMSP.
#define FQ_PITCH 400
#define FV_PITCH 272
#define FQ_HALF  (128*FQ_PITCH)           // 51200
#define FK_HALF  (32*FQ_PITCH)            // 12800
#define FV_HALF  (32*FV_PITCH)            // 8704
#define F_OFF_K  (2*FQ_HALF)              // 102400
#define F_K_STAGE (2*FK_HALF)             // 25600
#define F_OFF_V  (F_OFF_K + 2*F_K_STAGE)  // 153600
#define F_V_STAGE (2*FV_HALF)             // 17408
#define FLASH_SMEM (F_OFF_V + 2*F_V_STAGE) // 188416

__global__ void __launch_bounds__(256, 1) flash_mma(
    const __nv_bfloat16* __restrict__ qh, const __nv_bfloat16* __restrict__ ql,
    const __nv_bfloat16* __restrict__ kh, const __nv_bfloat16* __restrict__ kl,
    const __nv_bfloat16* __restrict__ vh, const __nv_bfloat16* __restrict__ vl,
    __nv_bfloat16* __restrict__ oh, __nv_bfloat16* __restrict__ ol) {
    extern __shared__ char sm[];
    uint32_t sb = smem_u32(sm);

    int qt = (gridDim.x - 1) - blockIdx.x;   // heavy CTAs first
    int h = blockIdx.y, b = blockIdx.z;
    int q0 = qt * 128;
    int tid = threadIdx.x, lane = tid & 31, w = tid >> 5;
    int bh = b * NHh + h;

    const __nv_bfloat16* qhb = qh + ((size_t)bh * Ss + q0) * QKD;
    const __nv_bfloat16* qlb = ql + ((size_t)bh * Ss + q0) * QKD;
    const __nv_bfloat16* khb = kh + (size_t)bh * Ss * QKD;
    const __nv_bfloat16* klb = kl + (size_t)bh * Ss * QKD;
    const __nv_bfloat16* vhb = vh + (size_t)bh * Ss * VDIM;
    const __nv_bfloat16* vlb = vl + (size_t)bh * Ss * VDIM;

    // ---- load Q (128 rows, hi/lo) ----
#pragma unroll
    for (int i = 0; i < 12; i++) {
        int e = tid + i * 256;               // 3072 chunks per half
        int r = e / 24, c = e % 24;
        CP_ASYNC16(sb + r * FQ_PITCH + c * 16, qhb + (size_t)r * QKD + c * 8);
        CP_ASYNC16(sb + FQ_HALF + r * FQ_PITCH + c * 16, qlb + (size_t)r * QKD + c * 8);
    }

    auto load_kv = [&](int kt, int s) {
        int k0 = kt * 32;
        uint32_t kst = sb + F_OFF_K + s * F_K_STAGE;
        uint32_t vst = sb + F_OFF_V + s * F_V_STAGE;
#pragma unroll
        for (int i = 0; i < 3; i++) {
            int e = tid + i * 256;           // 768 chunks per half
            int r = e / 24, c = e % 24;
            CP_ASYNC16(kst + r * FQ_PITCH + c * 16, khb + (size_t)(k0 + r) * QKD + c * 8);
            CP_ASYNC16(kst + FK_HALF + r * FQ_PITCH + c * 16, klb + (size_t)(k0 + r) * QKD + c * 8);
        }
#pragma unroll
        for (int i = 0; i < 2; i++) {
            int e = tid + i * 256;           // 512 chunks per half
            int r = e >> 4, c = e & 15;
            CP_ASYNC16(vst + r * FV_PITCH + c * 16, vhb + (size_t)(k0 + r) * VDIM + c * 8);
            CP_ASYNC16(vst + FV_HALF + r * FV_PITCH + c * 16, vlb + (size_t)(k0 + r) * VDIM + c * 8);
        }
    };

    load_kv(0, 0);
    CP_COMMIT();                             // group: Q + tile0

    int a_r = w * 16 + (lane & 15);
    int a_c8 = (lane >> 4) << 3;
    int b_r = ((lane >> 4) << 3) + (lane & 7);   // + nb*16
    int b_c8 = ((lane >> 3) & 1) << 3;
    int vt_r = lane & 15;                        // + kk*16 (trans)
    int vt_c8 = (lane >> 4) << 3;                // + j2*16

    int g = lane >> 2, t4 = lane & 3;

    float m0 = -INFINITY, m1 = -INFINITY, l0 = 0.f, l1 = 0.f;
    float O[16][4];
#pragma unroll
    for (int j = 0; j < 16; j++)
#pragma unroll
        for (int k = 0; k < 4; k++) O[j][k] = 0.f;

    int qrow0 = q0 + w * 16 + g;
    int qrow1 = qrow0 + 8;

    int nkt = (q0 + 128) >> 5;               // kv tiles of 32

    for (int kt = 0; kt < nkt; kt++) {
        int s = kt & 1;
        if (kt + 1 < nkt) { load_kv(kt + 1, s ^ 1); CP_COMMIT(); CP_WAIT1(); }
        else              { CP_WAIT0(); }
        __syncthreads();

        uint32_t kst = sb + F_OFF_K + s * F_K_STAGE;
        uint32_t vst = sb + F_OFF_V + s * F_V_STAGE;
        int k0 = kt * 32;

        // ---- QK^T: warp computes 16x32 scores ----
        float sc[4][4];
#pragma unroll
        for (int j = 0; j < 4; j++)
#pragma unroll
            for (int k = 0; k < 4; k++) sc[j][k] = 0.f;

#pragma unroll
        for (int kk = 0; kk < 12; kk++) {
            uint32_t ah[4], al[4];
            uint32_t aoff = (uint32_t)(a_r * FQ_PITCH + (kk * 16 + a_c8) * 2);
            LDSM4(ah, sb + aoff);
            LDSM4(al, sb + FQ_HALF + aoff);
#pragma unroll
            for (int nb = 0; nb < 2; nb++) {
                uint32_t bhf[4], blf[4];
                uint32_t boff = (uint32_t)((nb * 16 + b_r) * FQ_PITCH + (kk * 16 + b_c8) * 2);
                LDSM4(bhf, kst + boff);
                LDSM4(blf, kst + FK_HALF + boff);
                MMA16816(sc[2*nb],   ah, bhf[0], bhf[1]);
                MMA16816(sc[2*nb],   ah, blf[0], blf[1]);
                MMA16816(sc[2*nb],   al, bhf[0], bhf[1]);
                MMA16816(sc[2*nb+1], ah, bhf[2], bhf[3]);
                MMA16816(sc[2*nb+1], ah, blf[2], blf[3]);
                MMA16816(sc[2*nb+1], al, bhf[2], bhf[3]);
            }
        }

        // ---- causal mask (only tiles that can cross the diagonal) ----
        if (k0 + 31 > q0) {
#pragma unroll
            for (int j = 0; j < 4; j++) {
                int col = k0 + j * 8 + t4 * 2;
                if (col     > qrow0) sc[j][0] = -INFINITY;
                if (col + 1 > qrow0) sc[j][1] = -INFINITY;
                if (col     > qrow1) sc[j][2] = -INFINITY;
                if (col + 1 > qrow1) sc[j][3] = -INFINITY;
            }
        }

        // ---- online softmax ----
        float rm0 = -INFINITY, rm1 = -INFINITY;
#pragma unroll
        for (int j = 0; j < 4; j++) {
            rm0 = fmaxf(rm0, fmaxf(sc[j][0], sc[j][1]));
            rm1 = fmaxf(rm1, fmaxf(sc[j][2], sc[j][3]));
        }
        rm0 = fmaxf(rm0, __shfl_xor_sync(0xffffffffu, rm0, 1));
        rm0 = fmaxf(rm0, __shfl_xor_sync(0xffffffffu, rm0, 2));
        rm1 = fmaxf(rm1, __shfl_xor_sync(0xffffffffu, rm1, 1));
        rm1 = fmaxf(rm1, __shfl_xor_sync(0xffffffffu, rm1, 2));
        float nm0 = fmaxf(m0, rm0), nm1 = fmaxf(m1, rm1);
        float rs0 = 0.f, rs1 = 0.f;
#pragma unroll
        for (int j = 0; j < 4; j++) {
            sc[j][0] = __expf(sc[j][0] - nm0);
            sc[j][1] = __expf(sc[j][1] - nm0);
            sc[j][2] = __expf(sc[j][2] - nm1);
            sc[j][3] = __expf(sc[j][3] - nm1);
            rs0 += sc[j][0] + sc[j][1];
            rs1 += sc[j][2] + sc[j][3];
        }
        rs0 += __shfl_xor_sync(0xffffffffu, rs0, 1);
        rs0 += __shfl_xor_sync(0xffffffffu, rs0, 2);
        rs1 += __shfl_xor_sync(0xffffffffu, rs1, 1);
        rs1 += __shfl_xor_sync(0xffffffffu, rs1, 2);
        float al0 = __expf(m0 - nm0), al1 = __expf(m1 - nm1);
        l0 = l0 * al0 + rs0; l1 = l1 * al1 + rs1;
        m0 = nm0; m1 = nm1;
#pragma unroll
        for (int j = 0; j < 16; j++) {
            O[j][0] *= al0; O[j][1] *= al0;
            O[j][2] *= al1; O[j][3] *= al1;
        }

        // ---- P -> bf16 hi/lo fragments ----
        uint32_t ph2[4][2], pl2[4][2];
#pragma unroll
        for (int j = 0; j < 4; j++) {
            __nv_bfloat162 p01 = __floats2bfloat162_rn(sc[j][0], sc[j][1]);
            __nv_bfloat162 p23 = __floats2bfloat162_rn(sc[j][2], sc[j][3]);
            ph2[j][0] = *(uint32_t*)&p01;
            ph2[j][1] = *(uint32_t*)&p23;
            float h0 = sc[j][0] - __bfloat162float(p01.x);
            float h1 = sc[j][1] - __bfloat162float(p01.y);
            float h2 = sc[j][2] - __bfloat162float(p23.x);
            float h3 = sc[j][3] - __bfloat162float(p23.y);
            __nv_bfloat162 q01 = __floats2bfloat162_rn(h0, h1);
            __nv_bfloat162 q23 = __floats2bfloat162_rn(h2, h3);
            pl2[j][0] = *(uint32_t*)&q01;
            pl2[j][1] = *(uint32_t*)&q23;
        }

        // ---- O += P @ V ----
#pragma unroll
        for (int kk = 0; kk < 2; kk++) {
            uint32_t ah[4] = { ph2[2*kk][0], ph2[2*kk][1], ph2[2*kk+1][0], ph2[2*kk+1][1] };
            uint32_t al[4] = { pl2[2*kk][0], pl2[2*kk][1], pl2[2*kk+1][0], pl2[2*kk+1][1] };
#pragma unroll
            for (int j2 = 0; j2 < 8; j2++) {
                uint32_t vhf[4], vlf[4];
                uint32_t voff = (uint32_t)((kk * 16 + vt_r) * FV_PITCH + (j2 * 16 + vt_c8) * 2);
                LDSM4T(vhf, vst + voff);
                LDSM4T(vlf, vst + FV_HALF + voff);
                MMA16816(O[2*j2],   ah, vhf[0], vhf[1]);
                MMA16816(O[2*j2],   al, vhf[0], vhf[1]);
                MMA16816(O[2*j2],   ah, vlf[0], vlf[1]);
                MMA16816(O[2*j2+1], ah, vhf[2], vhf[3]);
                MMA16816(O[2*j2+1], al, vhf[2], vhf[3]);
                MMA16816(O[2*j2+1], ah, vlf[2], vlf[3]);
            }
        }
        __syncthreads();
    }

    // ---- epilogue: hi/lo bf16 directly ----
    float inv0 = 1.f / l0, inv1 = 1.f / l1;
    size_t ob0 = ((size_t)(b * Ss + qrow0)) * (NHh * VDIM) + h * VDIM;
    size_t ob1 = ((size_t)(b * Ss + qrow1)) * (NHh * VDIM) + h * VDIM;
#pragma unroll
    for (int j = 0; j < 16; j++) {
        int d = j * 8 + t4 * 2;
        __nv_bfloat16 h0, l0v, h1, l1v;
        split_hl(O[j][0] * inv0, h0, l0v);
        split_hl(O[j][1] * inv0, h1, l1v);
        *(__nv_bfloat162*)(oh + ob0 + d) = __nv_bfloat162(h0, h1);
        *(__nv_bfloat162*)(ol + ob0 + d) = __nv_bfloat162(l0v, l1v);
        split_hl(O[j][2] * inv1, h0, l0v);
        split_hl(O[j][3] * inv1, h1, l1v);
        *(__nv_bfloat162*)(oh + ob1 + d) = __nv_bfloat162(h0, h1);
        *(__nv_bfloat162*)(ol + ob1 + d) = __nv_bfloat162(l0v, l1v);
    }
}

// ================= launch =================
extern "C" void kernel_launch(void* const* d_in, const int* in_sizes, int n_in,
                              void* d_out, int out_size) {
    const float* hs     = (const float*)d_in[0];
    const int*   pos    = (const int*)  d_in[1];
    const float* w_q_a  = (const float*)d_in[3];
    const float* q_ln   = (const float*)d_in[4];
    const float* w_q_b  = (const float*)d_in[5];
    const float* w_kv_a = (const float*)d_in[6];
    const float* kv_ln  = (const float*)d_in[7];
    const float* w_kv_b = (const float*)d_in[8];
    const float* w_o    = (const float*)d_in[9];
    float* out = (float*)d_out;

    float *qc, *q, *kvt;
    cudaGetSymbolAddress((void**)&qc,    g_qc);
    cudaGetSymbolAddress((void**)&q,     g_q);
    cudaGetSymbolAddress((void**)&kvt,   g_kvt);

    __nv_bfloat16 *hs_h,*hs_l,*qc_h,*qc_l,*kvc_h,*kvc_l,*at_h,*at_l;
    __nv_bfloat16 *wqa_h,*wqa_l,*wqb_h,*wqb_l,*wkva_h,*wkva_l,*wkvb_h,*wkvb_l,*wo_h,*wo_l;
    __nv_bfloat16 *qfh,*qfl,*kfh,*kfl,*vfh,*vfl;
    cudaGetSymbolAddress((void**)&hs_h,  g_hs_h);  cudaGetSymbolAddress((void**)&hs_l,  g_hs_l);
    cudaGetSymbolAddress((void**)&qc_h,  g_qc_h);  cudaGetSymbolAddress((void**)&qc_l,  g_qc_l);
    cudaGetSymbolAddress((void**)&kvc_h, g_kvc_h); cudaGetSymbolAddress((void**)&kvc_l, g_kvc_l);
    cudaGetSymbolAddress((void**)&at_h,  g_at_h);  cudaGetSymbolAddress((void**)&at_l,  g_at_l);
    cudaGetSymbolAddress((void**)&wqa_h, g_wqa_h); cudaGetSymbolAddress((void**)&wqa_l, g_wqa_l);
    cudaGetSymbolAddress((void**)&wqb_h, g_wqb_h); cudaGetSymbolAddress((void**)&wqb_l, g_wqb_l);
    cudaGetSymbolAddress((void**)&wkva_h,g_wkva_h);cudaGetSymbolAddress((void**)&wkva_l,g_wkva_l);
    cudaGetSymbolAddress((void**)&wkvb_h,g_wkvb_h);cudaGetSymbolAddress((void**)&wkvb_l,g_wkvb_l);
    cudaGetSymbolAddress((void**)&wo_h,  g_wo_h);  cudaGetSymbolAddress((void**)&wo_l,  g_wo_l);
    cudaGetSymbolAddress((void**)&qfh,   g_qfh);   cudaGetSymbolAddress((void**)&qfl,   g_qfl);
    cudaGetSymbolAddress((void**)&kfh,   g_kfh);   cudaGetSymbolAddress((void**)&kfl,   g_kfl);
    cudaGetSymbolAddress((void**)&vfh,   g_vfh);   cudaGetSymbolAddress((void**)&vfl,   g_vfl);

    cudaFuncSetAttribute(mma_gemm_t<0>, cudaFuncAttributeMaxDynamicSharedMemorySize, GEMM_SMEM);
    cudaFuncSetAttribute(mma_gemm_t<1>, cudaFuncAttributeMaxDynamicSharedMemorySize, GEMM_SMEM);
    cudaFuncSetAttribute(flash_mma, cudaFuncAttributeMaxDynamicSharedMemorySize, FLASH_SMEM);

    dim3 tb(32, 8);

    transpose_split<<<dim3(QLORA/32, HID/32), tb>>>(w_q_a, wqa_h, wqa_l, HID, QLORA);
    transpose_split<<<dim3((NHh*QKD)/32, QLORA/32), tb>>>(w_q_b, wqb_h, wqb_l, QLORA, NHh*QKD);
    transpose_split<<<dim3(WKVA_NPAD/32, HID/32), tb>>>(w_kv_a, wkva_h, wkva_l, HID, KVLORA+ROPED);
    transpose_split<<<dim3((NHh*(NOPE+VDIM))/32, KVLORA/32), tb>>>(w_kv_b, wkvb_h, wkvb_l, KVLORA, NHh*(NOPE+VDIM));
    transpose_split<<<dim3(HID/32, (NHh*VDIM)/32), tb>>>(w_o, wo_h, wo_l, NHh*VDIM, HID);
    convert_split<<<(ROWS*(size_t)HID/4 + 255)/256, 256>>>(hs, hs_h, hs_l, (size_t)ROWS*HID);

    // G1: qc = hs @ w_q_a ; fused rmsnorm->hi/lo
    mma_gemm_t<0><<<dim3(QLORA/128, ROWS/128), 256, GEMM_SMEM>>>(
        hs_h, hs_l, wqa_h, wqa_l, qc, nullptr, nullptr, nullptr, nullptr, ROWS, QLORA, HID);
    rmsnorm_split<<<ROWS, 256>>>(qc, q_ln, qc_h, qc_l, QLORA);

    // G2: q = qc @ w_q_b ; fused rope+scale+prep
    mma_gemm_t<0><<<dim3((NHh*QKD)/128, ROWS/128), 256, GEMM_SMEM>>>(
        qc_h, qc_l, wqb_h, wqb_l, q, nullptr, nullptr, nullptr, nullptr, ROWS, NHh*QKD, QLORA);
    rope_prep_q<<<ROWS, 256>>>(q, pos, qfh, qfl);

    // G3: kvt = hs @ w_kv_a ; fused split
    mma_gemm_t<0><<<dim3(WKVA_NPAD/128, ROWS/128), 256, GEMM_SMEM>>>(
        hs_h, hs_l, wkva_h, wkva_l, kvt, nullptr, nullptr, nullptr, nullptr, ROWS, KVLORA+ROPED, HID);
    kv_split2<<<ROWS, 256>>>(kvt, kv_ln, pos, kvc_h, kvc_l, kfh, kfl);

    // G4: kv = kvc @ w_kv_b -> scatter to flash layout
    mma_gemm_t<1><<<dim3((NHh*(NOPE+VDIM))/128, ROWS/128), 256, GEMM_SMEM>>>(
        kvc_h, kvc_l, wkvb_h, wkvb_l, nullptr, kfh, kfl, vfh, vfl, ROWS, NHh*(NOPE+VDIM), KVLORA);

    // attention (q-tile 128, 256 threads)
    flash_mma<<<dim3(Ss/128, NHh, Bb), 256, FLASH_SMEM>>>(qfh, qfl, kfh, kfl, vfh, vfl, at_h, at_l);

    // G5: out = attn @ w_o
    mma_gemm_t<0><<<dim3(HID/128, ROWS/128), 256, GEMM_SMEM>>>(
        at_h, at_l, wo_h, wo_l, out, nullptr, nullptr, nullptr, nullptr, ROWS, HID, HID);
}

// round 7
// speedup vs baseline: 2.3776x; 2.3776x over previous
#include <cuda_runtime.h>
#include <cuda_fp16.h>
#include <math.h>
#include <cstdint>

// ---------------- problem constants ----------------
#define Bb   2
#define Ss   2048
#define HID  2048
#define NHh  16
#define QLORA 1536
#define KVLORA 512
#define NOPE 128
#define ROPED 64
#define VDIM 128
#define QKD  192
#define ROWS (Bb*Ss)          // 4096
#define WKVA_NPAD 640
#define SCALEF 0.07216878364870322f

// ---------------- fp32 scratch ----------------
__device__ float g_qc   [(size_t)ROWS * QLORA];
__device__ float g_q    [(size_t)ROWS * NHh * QKD];
__device__ float g_kvt  [(size_t)ROWS * (KVLORA+ROPED)];

// ---------------- fp16 activations ----------------
__device__ __half g_hs_h [(size_t)ROWS*HID];
__device__ __half g_qc_h [(size_t)ROWS*QLORA];
__device__ __half g_kvc_h[(size_t)ROWS*KVLORA];
__device__ __half g_at_h [(size_t)ROWS*NHh*VDIM];

// ---------------- fp16 transposed weights [N,K] ----------------
__device__ __half g_wqa_h [(size_t)QLORA*HID];
__device__ __half g_wqb_h [(size_t)(NHh*QKD)*QLORA];
__device__ __half g_wkva_h[(size_t)WKVA_NPAD*HID];
__device__ __half g_wkvb_h[(size_t)(NHh*(NOPE+VDIM))*KVLORA];
__device__ __half g_wo_h  [(size_t)HID*(NHh*VDIM)];

// ---------------- flash fp16 buffers, [b,h,s,d] ----------------
__device__ __half g_qfh[(size_t)ROWS*NHh*QKD];
__device__ __half g_kfh[(size_t)ROWS*NHh*QKD];
__device__ __half g_vfh[(size_t)ROWS*NHh*VDIM];

// ================= helpers =================
__device__ __forceinline__ uint32_t smem_u32(const void* p) {
    uint32_t a;
    asm("{ .reg .u64 t; cvta.to.shared.u64 t, %1; cvt.u32.u64 %0, t; }" : "=r"(a) : "l"(p));
    return a;
}

#define LDSM4(r, a) asm volatile( \
    "ldmatrix.sync.aligned.m8n8.x4.shared.b16 {%0,%1,%2,%3}, [%4];" \
    : "=r"((r)[0]),"=r"((r)[1]),"=r"((r)[2]),"=r"((r)[3]) : "r"(a))

#define LDSM4T(r, a) asm volatile( \
    "ldmatrix.sync.aligned.m8n8.x4.trans.shared.b16 {%0,%1,%2,%3}, [%4];" \
    : "=r"((r)[0]),"=r"((r)[1]),"=r"((r)[2]),"=r"((r)[3]) : "r"(a))

#define MMA16816(d, a, b0v, b1v) asm volatile( \
    "mma.sync.aligned.m16n8k16.row.col.f32.f16.f16.f32 " \
    "{%0,%1,%2,%3},{%4,%5,%6,%7},{%8,%9},{%0,%1,%2,%3};" \
    : "+f"((d)[0]),"+f"((d)[1]),"+f"((d)[2]),"+f"((d)[3]) \
    : "r"((a)[0]),"r"((a)[1]),"r"((a)[2]),"r"((a)[3]), "r"(b0v),"r"(b1v))

#define CP_ASYNC16(sa, ga) asm volatile( \
    "cp.async.cg.shared.global [%0], [%1], 16;" :: "r"(sa), "l"(ga))
#define CP_COMMIT() asm volatile("cp.async.commit_group;" ::: "memory")
#define CP_WAIT1()  asm volatile("cp.async.wait_group 1;" ::: "memory")
#define CP_WAIT0()  asm volatile("cp.async.wait_group 0;" ::: "memory")

// ================= fp16 HMMA GEMM, 3-stage pipeline =================
// C[M,N] = A[M,K] @ Bt[N,K]^T, single-pass fp16.
// MODE 0: fp32 C.  MODE 1: scatter -> kf (d<128, stride 192) | vf (stride 128).
#define BK 32
#define PITCH 40
#define TILE_B (128*PITCH*2)          // 10240
#define STAGE_B (2*TILE_B)            // 20480
#define NSTAGE 3
#define GEMM_SMEM (NSTAGE*STAGE_B)    // 61440

template<int MODE>
__global__ void __launch_bounds__(256, 2) mma_gemm_t(
    const __half* __restrict__ A, const __half* __restrict__ B,
    float* __restrict__ C,
    __half* __restrict__ P0, __half* __restrict__ P2,
    int M, int N, int K) {
    extern __shared__ char sm[];
    uint32_t sbase = smem_u32(sm);

    int tid = threadIdx.x, lane = tid & 31, wid = tid >> 5;
    int warpM = wid & 3, warpN = wid >> 2;
    int row0 = blockIdx.y * 128, col0 = blockIdx.x * 128;

    const __half* gA = A + (size_t)row0 * K;
    const __half* gB = B + (size_t)col0 * K;

    auto issue_loads = [&](int c, int s) {
        int k0 = c * BK;
        uint32_t st = sbase + s * STAGE_B;
#pragma unroll
        for (int j = 0; j < 2; j++) {
            int seg = tid + j * 256;
            int r = seg >> 2, cc = seg & 3;
            CP_ASYNC16(st + r * (PITCH * 2) + cc * 16, gA + (size_t)r * K + k0 + cc * 8);
            CP_ASYNC16(st + TILE_B + r * (PITCH * 2) + cc * 16, gB + (size_t)r * K + k0 + cc * 8);
        }
        CP_COMMIT();
    };

    float acc[2][8][4];
#pragma unroll
    for (int i = 0; i < 2; i++)
#pragma unroll
        for (int j = 0; j < 8; j++)
#pragma unroll
            for (int k = 0; k < 4; k++) acc[i][j][k] = 0.f;

    int a_r = warpM * 32 + (lane & 15);
    int a_c8 = (lane >> 4) << 3;
    int b_r = warpN * 64 + ((lane >> 4) << 3) + (lane & 7);
    int b_c8 = ((lane >> 3) & 1) << 3;

    auto compute = [&](int s) {
        uint32_t st = sbase + s * STAGE_B;
#pragma unroll
        for (int ki = 0; ki < 2; ki++) {
            uint32_t ah[2][4];
#pragma unroll
            for (int mi = 0; mi < 2; mi++) {
                uint32_t off = (uint32_t)((a_r + mi * 16) * (PITCH * 2) + (ki * 16 + a_c8) * 2);
                LDSM4(ah[mi], st + off);
            }
            uint32_t bh[4][4];
#pragma unroll
            for (int nb = 0; nb < 4; nb++) {
                uint32_t off = (uint32_t)((b_r + nb * 16) * (PITCH * 2) + (ki * 16 + b_c8) * 2);
                LDSM4(bh[nb], st + TILE_B + off);
            }
#pragma unroll
            for (int mi = 0; mi < 2; mi++)
#pragma unroll
                for (int nb = 0; nb < 4; nb++) {
                    MMA16816(acc[mi][2*nb],   ah[mi], bh[nb][0], bh[nb][1]);
                    MMA16816(acc[mi][2*nb+1], ah[mi], bh[nb][2], bh[nb][3]);
                }
        }
    };

    int nc = K / BK;
    issue_loads(0, 0);
    issue_loads(1, 1);
    for (int c = 0; c < nc; c++) {
        int s = c % NSTAGE;
        if (c + 1 < nc) { CP_WAIT1(); } else { CP_WAIT0(); }
        __syncthreads();
        if (c + 2 < nc) issue_loads(c + 2, (c + 2) % NSTAGE);
        compute(s);
    }

    int g = lane >> 2, t = lane & 3;
    if (MODE == 0) {
#pragma unroll
        for (int mi = 0; mi < 2; mi++)
#pragma unroll
            for (int n8 = 0; n8 < 8; n8++) {
                int col = col0 + warpN * 64 + n8 * 8 + t * 2;
                if (col < N) {
                    int r0 = row0 + warpM * 32 + mi * 16 + g;
                    float* p0 = C + (size_t)r0 * N + col;
                    p0[0] = acc[mi][n8][0]; p0[1] = acc[mi][n8][1];
                    float* p1 = p0 + (size_t)8 * N;
                    p1[0] = acc[mi][n8][2]; p1[1] = acc[mi][n8][3];
                }
            }
    } else {
        int hH = col0 >> 8;
        int isV = (col0 >> 7) & 1;
        __half* D = isV ? P2 : P0;
        int stride = isV ? VDIM : QKD;
#pragma unroll
        for (int mi = 0; mi < 2; mi++)
#pragma unroll
            for (int n8 = 0; n8 < 8; n8++) {
                int col = col0 + warpN * 64 + n8 * 8 + t * 2;
                int d = col & 127;
#pragma unroll
                for (int rr = 0; rr < 2; rr++) {
                    int r0 = row0 + warpM * 32 + mi * 16 + g + rr * 8;
                    int b = r0 >> 11, srow = r0 & 2047;
                    size_t o = ((size_t)(b * NHh + hH) * Ss + srow) * stride + d;
                    *(__half2*)(D + o) = __floats2half2_rn(acc[mi][n8][rr*2], acc[mi][n8][rr*2+1]);
                }
            }
    }
}

// ================= conversion / transpose kernels =================
__global__ void convert_h(const float* __restrict__ x, __half* __restrict__ h, size_t n) {
    size_t i = ((size_t)blockIdx.x * 256 + threadIdx.x) * 4;
    if (i >= n) return;
    float4 v = *(const float4*)(x + i);
    *(__half2*)(h + i)     = __floats2half2_rn(v.x, v.y);
    *(__half2*)(h + i + 2) = __floats2half2_rn(v.z, v.w);
}

__global__ void transpose_h(const float* __restrict__ W, __half* __restrict__ Th, int K, int N) {
    __shared__ float tile[32][33];
    int n0 = blockIdx.x * 32, k0 = blockIdx.y * 32;
    int tx = threadIdx.x, ty = threadIdx.y;
#pragma unroll
    for (int i = 0; i < 4; i++) {
        int k = k0 + ty + i * 8, n = n0 + tx;
        tile[ty + i * 8][tx] = (n < N) ? W[(size_t)k * N + n] : 0.f;
    }
    __syncthreads();
#pragma unroll
    for (int i = 0; i < 4; i++) {
        int n = n0 + ty + i * 8;
        Th[(size_t)n * K + k0 + tx] = __float2half(tile[tx][ty + i * 8]);
    }
}

// ================= fused rmsnorm -> fp16 =================
__global__ void rmsnorm_h(const float* __restrict__ x, const float* __restrict__ w,
                          __half* __restrict__ oh, int L) {
    __shared__ float red[256];
    int tid = threadIdx.x;
    const float* r = x + (size_t)blockIdx.x * L;
    float ss = 0.f;
    for (int i = tid; i < L; i += 256) { float v = r[i]; ss += v * v; }
    red[tid] = ss; __syncthreads();
    for (int s = 128; s > 0; s >>= 1) { if (tid < s) red[tid] += red[tid + s]; __syncthreads(); }
    float scale = rsqrtf(red[0] / (float)L + 1e-6f);
    for (int i = tid; i < L; i += 256)
        oh[(size_t)blockIdx.x * L + i] = __float2half(r[i] * scale * w[i]);
}

// ================= fused kv split =================
__global__ void kv_split2(const float* __restrict__ kvt, const float* __restrict__ w,
                          const int* __restrict__ pos,
                          __half* __restrict__ kvch, __half* __restrict__ kfh) {
    __shared__ float red[256];
    __shared__ float rop[64];
    int tid = threadIdx.x, row = blockIdx.x;
    const float* r = kvt + (size_t)row * (KVLORA + ROPED);
    float ss = 0.f;
    for (int i = tid; i < KVLORA; i += 256) { float v = r[i]; ss += v * v; }
    red[tid] = ss; __syncthreads();
    for (int s = 128; s > 0; s >>= 1) { if (tid < s) red[tid] += red[tid + s]; __syncthreads(); }
    float scale = rsqrtf(red[0] / (float)KVLORA + 1e-6f);
    for (int i = tid; i < KVLORA; i += 256)
        kvch[(size_t)row * KVLORA + i] = __float2half(r[i] * scale * w[i]);
    if (tid < 32) {
        float p = (float)pos[row];
        float inv_freq = powf(10000.f, -(float)tid / 32.f);
        float ang = p * inv_freq;
        float c = cosf(ang), s = sinf(ang);
        float x1 = r[KVLORA + tid];
        float x2 = r[KVLORA + 32 + tid];
        rop[tid]      = x1 * c - x2 * s;
        rop[tid + 32] = x2 * c + x1 * s;
    }
    __syncthreads();
    int b = row >> 11, srow = row & 2047;
    for (int e = tid; e < NHh * ROPED; e += 256) {
        int h = e >> 6, d = e & 63;
        size_t o = ((size_t)(b * NHh + h) * Ss + srow) * QKD + NOPE + d;
        kfh[o] = __float2half(rop[d]);
    }
}

// ================= fused rope+scale+prep for Q =================
__global__ void rope_prep_q(const float* __restrict__ q, const int* __restrict__ pos,
                            __half* __restrict__ qfh) {
    int row = blockIdx.x;
    int b = row >> 11, srow = row & 2047;
    float p = (float)pos[row];
    const float* qr = q + (size_t)row * (NHh * QKD);
    for (int e = threadIdx.x; e < NHh * QKD; e += 256) {
        int h = e / QKD, d = e % QKD;
        float v;
        if (d < NOPE) v = qr[e];
        else {
            int i = d - NOPE;
            int j = i & 31;
            float inv_freq = powf(10000.f, -(float)j / 32.f);
            float ang = p * inv_freq;
            float c = cosf(ang), s = sinf(ang);
            float x1 = qr[h * QKD + NOPE + j];
            float x2 = qr[h * QKD + NOPE + 32 + j];
            v = (i < 32) ? (x1 * c - x2 * s) : (x2 * c + x1 * s);
        }
        size_t o = ((size_t)(b * NHh + h) * Ss + srow) * QKD + d;
        qfh[o] = __float2half(v * SCALEF);
    }
}

// ================= fp16 tensor-core flash attention =================
// q-tile 128, kv-tile 32, 256 threads (8 warps x 16 q rows).
#define FQ_PITCH 400
#define FV_PITCH 272
#define FQ_SZ    (128*FQ_PITCH)           // 51200
#define FK_SZ    (32*FQ_PITCH)            // 12800
#define FV_SZ    (32*FV_PITCH)            // 8704
#define F_OFF_K  FQ_SZ
#define F_OFF_V  (F_OFF_K + 2*FK_SZ)      // 76800
#define FLASH_SMEM (F_OFF_V + 2*FV_SZ)    // 94208

__global__ void __launch_bounds__(256, 2) flash_mma(
    const __half* __restrict__ qh, const __half* __restrict__ kh,
    const __half* __restrict__ vh, __half* __restrict__ oh) {
    extern __shared__ char sm[];
    uint32_t sb = smem_u32(sm);

    int qt = (gridDim.x - 1) - blockIdx.x;   // heavy CTAs first
    int h = blockIdx.y, b = blockIdx.z;
    int q0 = qt * 128;
    int tid = threadIdx.x, lane = tid & 31, w = tid >> 5;
    int bh = b * NHh + h;

    const __half* qhb = qh + ((size_t)bh * Ss + q0) * QKD;
    const __half* khb = kh + (size_t)bh * Ss * QKD;
    const __half* vhb = vh + (size_t)bh * Ss * VDIM;

    // ---- load Q ----
#pragma unroll
    for (int i = 0; i < 12; i++) {
        int e = tid + i * 256;               // 3072 chunks
        int r = e / 24, c = e % 24;
        CP_ASYNC16(sb + r * FQ_PITCH + c * 16, qhb + (size_t)r * QKD + c * 8);
    }

    auto load_kv = [&](int kt, int s) {
        int k0 = kt * 32;
        uint32_t kst = sb + F_OFF_K + s * FK_SZ;
        uint32_t vst = sb + F_OFF_V + s * FV_SZ;
#pragma unroll
        for (int i = 0; i < 3; i++) {
            int e = tid + i * 256;           // 768 chunks
            int r = e / 24, c = e % 24;
            CP_ASYNC16(kst + r * FQ_PITCH + c * 16, khb + (size_t)(k0 + r) * QKD + c * 8);
        }
        {
            int e = tid * 2;                 // 512 chunks, 2 per thread
            int r = e >> 4, c = e & 15;
            CP_ASYNC16(vst + r * FV_PITCH + c * 16, vhb + (size_t)(k0 + r) * VDIM + c * 8);
            CP_ASYNC16(vst + r * FV_PITCH + (c + 1) * 16, vhb + (size_t)(k0 + r) * VDIM + (c + 1) * 8);
        }
    };

    load_kv(0, 0);
    CP_COMMIT();

    int a_r = w * 16 + (lane & 15);
    int a_c8 = (lane >> 4) << 3;
    int b_r = ((lane >> 4) << 3) + (lane & 7);
    int b_c8 = ((lane >> 3) & 1) << 3;
    int vt_r = lane & 15;
    int vt_c8 = (lane >> 4) << 3;

    int g = lane >> 2, t4 = lane & 3;

    float m0 = -INFINITY, m1 = -INFINITY, l0 = 0.f, l1 = 0.f;
    float O[16][4];
#pragma unroll
    for (int j = 0; j < 16; j++)
#pragma unroll
        for (int k = 0; k < 4; k++) O[j][k] = 0.f;

    int qrow0 = q0 + w * 16 + g;
    int qrow1 = qrow0 + 8;

    int nkt = (q0 + 128) >> 5;

    for (int kt = 0; kt < nkt; kt++) {
        int s = kt & 1;
        if (kt + 1 < nkt) { load_kv(kt + 1, s ^ 1); CP_COMMIT(); CP_WAIT1(); }
        else              { CP_WAIT0(); }
        __syncthreads();

        uint32_t kst = sb + F_OFF_K + s * FK_SZ;
        uint32_t vst = sb + F_OFF_V + s * FV_SZ;
        int k0 = kt * 32;

        // ---- QK^T: warp computes 16x32 scores ----
        float sc[4][4];
#pragma unroll
        for (int j = 0; j < 4; j++)
#pragma unroll
            for (int k = 0; k < 4; k++) sc[j][k] = 0.f;

#pragma unroll
        for (int kk = 0; kk < 12; kk++) {
            uint32_t ah[4];
            LDSM4(ah, sb + (uint32_t)(a_r * FQ_PITCH + (kk * 16 + a_c8) * 2));
#pragma unroll
            for (int nb = 0; nb < 2; nb++) {
                uint32_t bhf[4];
                LDSM4(bhf, kst + (uint32_t)((nb * 16 + b_r) * FQ_PITCH + (kk * 16 + b_c8) * 2));
                MMA16816(sc[2*nb],   ah, bhf[0], bhf[1]);
                MMA16816(sc[2*nb+1], ah, bhf[2], bhf[3]);
            }
        }

        // ---- causal mask ----
        if (k0 + 31 > q0) {
#pragma unroll
            for (int j = 0; j < 4; j++) {
                int col = k0 + j * 8 + t4 * 2;
                if (col     > qrow0) sc[j][0] = -INFINITY;
                if (col + 1 > qrow0) sc[j][1] = -INFINITY;
                if (col     > qrow1) sc[j][2] = -INFINITY;
                if (col + 1 > qrow1) sc[j][3] = -INFINITY;
            }
        }

        // ---- online softmax ----
        float rm0 = -INFINITY, rm1 = -INFINITY;
#pragma unroll
        for (int j = 0; j < 4; j++) {
            rm0 = fmaxf(rm0, fmaxf(sc[j][0], sc[j][1]));
            rm1 = fmaxf(rm1, fmaxf(sc[j][2], sc[j][3]));
        }
        rm0 = fmaxf(rm0, __shfl_xor_sync(0xffffffffu, rm0, 1));
        rm0 = fmaxf(rm0, __shfl_xor_sync(0xffffffffu, rm0, 2));
        rm1 = fmaxf(rm1, __shfl_xor_sync(0xffffffffu, rm1, 1));
        rm1 = fmaxf(rm1, __shfl_xor_sync(0xffffffffu, rm1, 2));
        float nm0 = fmaxf(m0, rm0), nm1 = fmaxf(m1, rm1);
        float rs0 = 0.f, rs1 = 0.f;
#pragma unroll
        for (int j = 0; j < 4; j++) {
            sc[j][0] = __expf(sc[j][0] - nm0);
            sc[j][1] = __expf(sc[j][1] - nm0);
            sc[j][2] = __expf(sc[j][2] - nm1);
            sc[j][3] = __expf(sc[j][3] - nm1);
            rs0 += sc[j][0] + sc[j][1];
            rs1 += sc[j][2] + sc[j][3];
        }
        rs0 += __shfl_xor_sync(0xffffffffu, rs0, 1);
        rs0 += __shfl_xor_sync(0xffffffffu, rs0, 2);
        rs1 += __shfl_xor_sync(0xffffffffu, rs1, 1);
        rs1 += __shfl_xor_sync(0xffffffffu, rs1, 2);
        float al0 = __expf(m0 - nm0), al1 = __expf(m1 - nm1);
        l0 = l0 * al0 + rs0; l1 = l1 * al1 + rs1;
        m0 = nm0; m1 = nm1;
#pragma unroll
        for (int j = 0; j < 16; j++) {
            O[j][0] *= al0; O[j][1] *= al0;
            O[j][2] *= al1; O[j][3] *= al1;
        }

        // ---- P -> fp16 fragments ----
        uint32_t ph2[4][2];
#pragma unroll
        for (int j = 0; j < 4; j++) {
            __half2 p01 = __floats2half2_rn(sc[j][0], sc[j][1]);
            __half2 p23 = __floats2half2_rn(sc[j][2], sc[j][3]);
            ph2[j][0] = *(uint32_t*)&p01;
            ph2[j][1] = *(uint32_t*)&p23;
        }

        // ---- O += P @ V ----
#pragma unroll
        for (int kk = 0; kk < 2; kk++) {
            uint32_t ah[4] = { ph2[2*kk][0], ph2[2*kk][1], ph2[2*kk+1][0], ph2[2*kk+1][1] };
#pragma unroll
            for (int j2 = 0; j2 < 8; j2++) {
                uint32_t vhf[4];
                LDSM4T(vhf, vst + (uint32_t)((kk * 16 + vt_r) * FV_PITCH + (j2 * 16 + vt_c8) * 2));
                MMA16816(O[2*j2],   ah, vhf[0], vhf[1]);
                MMA16816(O[2*j2+1], ah, vhf[2], vhf[3]);
            }
        }
        __syncthreads();
    }

    // ---- epilogue: fp16 directly (A operand of G5) ----
    float inv0 = 1.f / l0, inv1 = 1.f / l1;
    size_t ob0 = ((size_t)(b * Ss + qrow0)) * (NHh * VDIM) + h * VDIM;
    size_t ob1 = ((size_t)(b * Ss + qrow1)) * (NHh * VDIM) + h * VDIM;
#pragma unroll
    for (int j = 0; j < 16; j++) {
        int d = j * 8 + t4 * 2;
        *(__half2*)(oh + ob0 + d) = __floats2half2_rn(O[j][0] * inv0, O[j][1] * inv0);
        *(__half2*)(oh + ob1 + d) = __floats2half2_rn(O[j][2] * inv1, O[j][3] * inv1);
    }
}

// ================= launch =================
extern "C" void kernel_launch(void* const* d_in, const int* in_sizes, int n_in,
                              void* d_out, int out_size) {
    const float* hs     = (const float*)d_in[0];
    const int*   pos    = (const int*)  d_in[1];
    const float* w_q_a  = (const float*)d_in[3];
    const float* q_ln   = (const float*)d_in[4];
    const float* w_q_b  = (const float*)d_in[5];
    const float* w_kv_a = (const float*)d_in[6];
    const float* kv_ln  = (const float*)d_in[7];
    const float* w_kv_b = (const float*)d_in[8];
    const float* w_o    = (const float*)d_in[9];
    float* out = (float*)d_out;

    float *qc, *q, *kvt;
    cudaGetSymbolAddress((void**)&qc,  g_qc);
    cudaGetSymbolAddress((void**)&q,   g_q);
    cudaGetSymbolAddress((void**)&kvt, g_kvt);

    __half *hs_h,*qc_h,*kvc_h,*at_h;
    __half *wqa_h,*wqb_h,*wkva_h,*wkvb_h,*wo_h;
    __half *qfh,*kfh,*vfh;
    cudaGetSymbolAddress((void**)&hs_h,  g_hs_h);
    cudaGetSymbolAddress((void**)&qc_h,  g_qc_h);
    cudaGetSymbolAddress((void**)&kvc_h, g_kvc_h);
    cudaGetSymbolAddress((void**)&at_h,  g_at_h);
    cudaGetSymbolAddress((void**)&wqa_h, g_wqa_h);
    cudaGetSymbolAddress((void**)&wqb_h, g_wqb_h);
    cudaGetSymbolAddress((void**)&wkva_h,g_wkva_h);
    cudaGetSymbolAddress((void**)&wkvb_h,g_wkvb_h);
    cudaGetSymbolAddress((void**)&wo_h,  g_wo_h);
    cudaGetSymbolAddress((void**)&qfh,   g_qfh);
    cudaGetSymbolAddress((void**)&kfh,   g_kfh);
    cudaGetSymbolAddress((void**)&vfh,   g_vfh);

    cudaFuncSetAttribute(mma_gemm_t<0>, cudaFuncAttributeMaxDynamicSharedMemorySize, GEMM_SMEM);
    cudaFuncSetAttribute(mma_gemm_t<1>, cudaFuncAttributeMaxDynamicSharedMemorySize, GEMM_SMEM);
    cudaFuncSetAttribute(flash_mma, cudaFuncAttributeMaxDynamicSharedMemorySize, FLASH_SMEM);

    dim3 tb(32, 8);

    transpose_h<<<dim3(QLORA/32, HID/32), tb>>>(w_q_a, wqa_h, HID, QLORA);
    transpose_h<<<dim3((NHh*QKD)/32, QLORA/32), tb>>>(w_q_b, wqb_h, QLORA, NHh*QKD);
    transpose_h<<<dim3(WKVA_NPAD/32, HID/32), tb>>>(w_kv_a, wkva_h, HID, KVLORA+ROPED);
    transpose_h<<<dim3((NHh*(NOPE+VDIM))/32, KVLORA/32), tb>>>(w_kv_b, wkvb_h, KVLORA, NHh*(NOPE+VDIM));
    transpose_h<<<dim3(HID/32, (NHh*VDIM)/32), tb>>>(w_o, wo_h, NHh*VDIM, HID);
    convert_h<<<(ROWS*(size_t)HID/4 + 255)/256, 256>>>(hs, hs_h, (size_t)ROWS*HID);

    // G1: qc = hs @ w_q_a ; fused rmsnorm->fp16
    mma_gemm_t<0><<<dim3(QLORA/128, ROWS/128), 256, GEMM_SMEM>>>(
        hs_h, wqa_h, qc, nullptr, nullptr, ROWS, QLORA, HID);
    rmsnorm_h<<<ROWS, 256>>>(qc, q_ln, qc_h, QLORA);

    // G2: q = qc @ w_q_b ; fused rope+scale+prep
    mma_gemm_t<0><<<dim3((NHh*QKD)/128, ROWS/128), 256, GEMM_SMEM>>>(
        qc_h, wqb_h, q, nullptr, nullptr, ROWS, NHh*QKD, QLORA);
    rope_prep_q<<<ROWS, 256>>>(q, pos, qfh);

    // G3: kvt = hs @ w_kv_a ; fused split
    mma_gemm_t<0><<<dim3(WKVA_NPAD/128, ROWS/128), 256, GEMM_SMEM>>>(
        hs_h, wkva_h, kvt, nullptr, nullptr, ROWS, KVLORA+ROPED, HID);
    kv_split2<<<ROWS, 256>>>(kvt, kv_ln, pos, kvc_h, kfh);

    // G4: kv = kvc @ w_kv_b -> scatter to flash layout
    mma_gemm_t<1><<<dim3((NHh*(NOPE+VDIM))/128, ROWS/128), 256, GEMM_SMEM>>>(
        kvc_h, wkvb_h, nullptr, kfh, vfh, ROWS, NHh*(NOPE+VDIM), KVLORA);

    // attention
    flash_mma<<<dim3(Ss/128, NHh, Bb), 256, FLASH_SMEM>>>(qfh, kfh, vfh, at_h);

    // G5: out = attn @ w_o
    mma_gemm_t<0><<<dim3(HID/128, ROWS/128), 256, GEMM_SMEM>>>(
        at_h, wo_h, out, nullptr, nullptr, ROWS, HID, HID);
}

// round 8
// speedup vs baseline: 2.6772x; 1.1260x over previous
#include <cuda_runtime.h>
#include <cuda_fp16.h>
#include <math.h>
#include <cstdint>

// ---------------- problem constants ----------------
#define Bb   2
#define Ss   2048
#define HID  2048
#define NHh  16
#define QLORA 1536
#define KVLORA 512
#define NOPE 128
#define ROPED 64
#define VDIM 128
#define QKD  192
#define ROWS (Bb*Ss)          // 4096
#define WKVA_NPAD 640
#define SCALEF 0.07216878364870322f
#define LN10K  9.210340371976184f

// ---------------- fp32 scratch ----------------
__device__ float g_qc   [(size_t)ROWS * QLORA];
__device__ float g_kvt  [(size_t)ROWS * (KVLORA+ROPED)];

// ---------------- fp16 activations ----------------
__device__ __half g_hs_h [(size_t)ROWS*HID];
__device__ __half g_qc_h [(size_t)ROWS*QLORA];
__device__ __half g_kvc_h[(size_t)ROWS*KVLORA];
__device__ __half g_at_h [(size_t)ROWS*NHh*VDIM];

// ---------------- fp16 transposed weights [N,K] ----------------
__device__ __half g_wqa_h [(size_t)QLORA*HID];
__device__ __half g_wqb_h [(size_t)(NHh*QKD)*QLORA];
__device__ __half g_wkva_h[(size_t)WKVA_NPAD*HID];
__device__ __half g_wkvb_h[(size_t)(NHh*(NOPE+VDIM))*KVLORA];
__device__ __half g_wo_h  [(size_t)HID*(NHh*VDIM)];

// ---------------- flash fp16 buffers, [b,h,s,d] ----------------
__device__ __half g_qfh[(size_t)ROWS*NHh*QKD];
__device__ __half g_kfh[(size_t)ROWS*NHh*QKD];
__device__ __half g_vfh[(size_t)ROWS*NHh*VDIM];

// ================= helpers =================
__device__ __forceinline__ uint32_t smem_u32(const void* p) {
    uint32_t a;
    asm("{ .reg .u64 t; cvta.to.shared.u64 t, %1; cvt.u32.u64 %0, t; }" : "=r"(a) : "l"(p));
    return a;
}

#define LDSM4(r, a) asm volatile( \
    "ldmatrix.sync.aligned.m8n8.x4.shared.b16 {%0,%1,%2,%3}, [%4];" \
    : "=r"((r)[0]),"=r"((r)[1]),"=r"((r)[2]),"=r"((r)[3]) : "r"(a))

#define LDSM4T(r, a) asm volatile( \
    "ldmatrix.sync.aligned.m8n8.x4.trans.shared.b16 {%0,%1,%2,%3}, [%4];" \
    : "=r"((r)[0]),"=r"((r)[1]),"=r"((r)[2]),"=r"((r)[3]) : "r"(a))

#define MMA16816(d, a, b0v, b1v) asm volatile( \
    "mma.sync.aligned.m16n8k16.row.col.f32.f16.f16.f32 " \
    "{%0,%1,%2,%3},{%4,%5,%6,%7},{%8,%9},{%0,%1,%2,%3};" \
    : "+f"((d)[0]),"+f"((d)[1]),"+f"((d)[2]),"+f"((d)[3]) \
    : "r"((a)[0]),"r"((a)[1]),"r"((a)[2]),"r"((a)[3]), "r"(b0v),"r"(b1v))

#define CP_ASYNC16(sa, ga) asm volatile( \
    "cp.async.cg.shared.global [%0], [%1], 16;" :: "r"(sa), "l"(ga))
#define CP_COMMIT() asm volatile("cp.async.commit_group;" ::: "memory")
#define CP_WAIT1()  asm volatile("cp.async.wait_group 1;" ::: "memory")
#define CP_WAIT0()  asm volatile("cp.async.wait_group 0;" ::: "memory")

// ================= fp16 HMMA GEMM mainloop (shared) =================
#define BK 32
#define PITCH 40
#define TILE_B (128*PITCH*2)          // 10240
#define STAGE_B (2*TILE_B)            // 20480
#define NSTAGE 3
#define GEMM_SMEM (NSTAGE*STAGE_B)    // 61440

// Computes acc[2][8][4] = A[128,K] @ B[128,K]^T tile for this CTA.
__device__ __forceinline__ void gemm_mainloop(
    const __half* __restrict__ gA, const __half* __restrict__ gB, int K,
    uint32_t sbase, float acc[2][8][4],
    int tid, int lane, int warpM, int warpN) {

    auto issue_loads = [&](int c, int s) {
        int k0 = c * BK;
        uint32_t st = sbase + s * STAGE_B;
#pragma unroll
        for (int j = 0; j < 2; j++) {
            int seg = tid + j * 256;
            int r = seg >> 2, cc = seg & 3;
            CP_ASYNC16(st + r * (PITCH * 2) + cc * 16, gA + (size_t)r * K + k0 + cc * 8);
            CP_ASYNC16(st + TILE_B + r * (PITCH * 2) + cc * 16, gB + (size_t)r * K + k0 + cc * 8);
        }
        CP_COMMIT();
    };

#pragma unroll
    for (int i = 0; i < 2; i++)
#pragma unroll
        for (int j = 0; j < 8; j++)
#pragma unroll
            for (int k = 0; k < 4; k++) acc[i][j][k] = 0.f;

    int a_r = warpM * 32 + (lane & 15);
    int a_c8 = (lane >> 4) << 3;
    int b_r = warpN * 64 + ((lane >> 4) << 3) + (lane & 7);
    int b_c8 = ((lane >> 3) & 1) << 3;

    auto compute = [&](int s) {
        uint32_t st = sbase + s * STAGE_B;
#pragma unroll
        for (int ki = 0; ki < 2; ki++) {
            uint32_t ah[2][4];
#pragma unroll
            for (int mi = 0; mi < 2; mi++) {
                uint32_t off = (uint32_t)((a_r + mi * 16) * (PITCH * 2) + (ki * 16 + a_c8) * 2);
                LDSM4(ah[mi], st + off);
            }
            uint32_t bh[4][4];
#pragma unroll
            for (int nb = 0; nb < 4; nb++) {
                uint32_t off = (uint32_t)((b_r + nb * 16) * (PITCH * 2) + (ki * 16 + b_c8) * 2);
                LDSM4(bh[nb], st + TILE_B + off);
            }
#pragma unroll
            for (int mi = 0; mi < 2; mi++)
#pragma unroll
                for (int nb = 0; nb < 4; nb++) {
                    MMA16816(acc[mi][2*nb],   ah[mi], bh[nb][0], bh[nb][1]);
                    MMA16816(acc[mi][2*nb+1], ah[mi], bh[nb][2], bh[nb][3]);
                }
        }
    };

    int nc = K / BK;
    issue_loads(0, 0);
    issue_loads(1, 1);
    for (int c = 0; c < nc; c++) {
        int s = c % NSTAGE;
        if (c + 1 < nc) { CP_WAIT1(); } else { CP_WAIT0(); }
        __syncthreads();
        if (c + 2 < nc) issue_loads(c + 2, (c + 2) % NSTAGE);
        compute(s);
    }
}

// ================= merged G1+G3: [qc | kvt] = hs @ [wqa | wkva] =============
__global__ void __launch_bounds__(256, 2) gemm_a(
    const __half* __restrict__ hs, const __half* __restrict__ wqa,
    const __half* __restrict__ wkva,
    float* __restrict__ qc, float* __restrict__ kvt) {
    extern __shared__ char sm[];
    uint32_t sbase = smem_u32(sm);
    int tid = threadIdx.x, lane = tid & 31, wid = tid >> 5;
    int warpM = wid & 3, warpN = wid >> 2;
    int row0 = blockIdx.y * 128;
    int bx = blockIdx.x;

    const __half* B;
    float* C; int cN, col0, Nlim;
    if (bx < 12) { col0 = bx * 128;        B = wqa  + (size_t)col0 * HID; C = qc;  cN = QLORA; Nlim = QLORA; }
    else         { col0 = (bx - 12) * 128; B = wkva + (size_t)col0 * HID; C = kvt; cN = KVLORA+ROPED; Nlim = KVLORA+ROPED; }

    float acc[2][8][4];
    gemm_mainloop(hs + (size_t)row0 * HID, B, HID, sbase, acc, tid, lane, warpM, warpN);

    int g = lane >> 2, t = lane & 3;
#pragma unroll
    for (int mi = 0; mi < 2; mi++)
#pragma unroll
        for (int n8 = 0; n8 < 8; n8++) {
            int col = col0 + warpN * 64 + n8 * 8 + t * 2;
            if (col < Nlim) {
                int r0 = row0 + warpM * 32 + mi * 16 + g;
                float* p0 = C + (size_t)r0 * cN + col;
                p0[0] = acc[mi][n8][0]; p0[1] = acc[mi][n8][1];
                float* p1 = p0 + (size_t)8 * cN;
                p1[0] = acc[mi][n8][2]; p1[1] = acc[mi][n8][3];
            }
        }
}

// ================= merged G2+G4 =================
// bx<24: q = qc_h @ wqb^T, fused rope+scale epilogue -> qfh [b,h,s,192]
// else : kv = kvc_h @ wkvb^T, scatter -> kfh (d<128) | vfh
__global__ void __launch_bounds__(256, 2) gemm_b(
    const __half* __restrict__ qch, const __half* __restrict__ wqb,
    const __half* __restrict__ kvch, const __half* __restrict__ wkvb,
    const int* __restrict__ pos,
    __half* __restrict__ qfh, __half* __restrict__ kfh, __half* __restrict__ vfh) {
    extern __shared__ char sm[];
    uint32_t sbase = smem_u32(sm);
    int tid = threadIdx.x, lane = tid & 31, wid = tid >> 5;
    int warpM = wid & 3, warpN = wid >> 2;
    int row0 = blockIdx.y * 128;
    int bx = blockIdx.x;
    int g = lane >> 2, t4 = lane & 3;

    if (bx < 24) {
        int col0 = bx * 128;
        float acc[2][8][4];
        gemm_mainloop(qch + (size_t)row0 * QLORA, wqb + (size_t)col0 * QLORA, QLORA,
                      sbase, acc, tid, lane, warpM, warpN);

        int colw = col0 + warpN * 64;       // 64-aligned block start
        int hH = colw / 192;
        int dbase = colw % 192;             // 0, 64, or 128
        if (dbase != 128) {
            // nope warp: plain scale
#pragma unroll
            for (int mi = 0; mi < 2; mi++)
#pragma unroll
                for (int rr = 0; rr < 2; rr++) {
                    int row = row0 + warpM * 32 + mi * 16 + g + rr * 8;
                    int b = row >> 11, srow = row & 2047;
                    size_t obase = ((size_t)(b * NHh + hH) * Ss + srow) * QKD;
#pragma unroll
                    for (int n8 = 0; n8 < 8; n8++) {
                        int d = dbase + n8 * 8 + t4 * 2;
                        *(__half2*)(qfh + obase + d) = __floats2half2_rn(
                            acc[mi][n8][rr*2] * SCALEF, acc[mi][n8][rr*2+1] * SCALEF);
                    }
                }
        } else {
            // rope warp: pair (j, j+32) lives in (n8, n8+4)
#pragma unroll
            for (int mi = 0; mi < 2; mi++)
#pragma unroll
                for (int rr = 0; rr < 2; rr++) {
                    int row = row0 + warpM * 32 + mi * 16 + g + rr * 8;
                    int b = row >> 11, srow = row & 2047;
                    float p = (float)pos[b * Ss + srow];
                    size_t obase = ((size_t)(b * NHh + hH) * Ss + srow) * QKD;
#pragma unroll
                    for (int n8 = 0; n8 < 4; n8++) {
                        int j0 = n8 * 8 + t4 * 2;
                        float if0 = __expf(-(float)j0 * (LN10K / 32.f));
                        float if1 = __expf(-(float)(j0 + 1) * (LN10K / 32.f));
                        float s0, c0, s1, c1;
                        __sincosf(p * if0, &s0, &c0);
                        __sincosf(p * if1, &s1, &c1);
                        float x1a = acc[mi][n8][rr*2],   x2a = acc[mi][n8+4][rr*2];
                        float x1b = acc[mi][n8][rr*2+1], x2b = acc[mi][n8+4][rr*2+1];
                        *(__half2*)(qfh + obase + 128 + j0) = __floats2half2_rn(
                            (x1a * c0 - x2a * s0) * SCALEF, (x1b * c1 - x2b * s1) * SCALEF);
                        *(__half2*)(qfh + obase + 160 + j0) = __floats2half2_rn(
                            (x2a * c0 + x1a * s0) * SCALEF, (x2b * c1 + x1b * s1) * SCALEF);
                    }
                }
        }
    } else {
        int col0 = (bx - 24) * 128;
        float acc[2][8][4];
        gemm_mainloop(kvch + (size_t)row0 * KVLORA, wkvb + (size_t)col0 * KVLORA, KVLORA,
                      sbase, acc, tid, lane, warpM, warpN);

        int hH = col0 >> 8;
        int isV = (col0 >> 7) & 1;
        __half* D = isV ? vfh : kfh;
        int stride = isV ? VDIM : QKD;
#pragma unroll
        for (int mi = 0; mi < 2; mi++)
#pragma unroll
            for (int n8 = 0; n8 < 8; n8++) {
                int col = col0 + warpN * 64 + n8 * 8 + t4 * 2;
                int d = col & 127;
#pragma unroll
                for (int rr = 0; rr < 2; rr++) {
                    int r0 = row0 + warpM * 32 + mi * 16 + g + rr * 8;
                    int b = r0 >> 11, srow = r0 & 2047;
                    size_t o = ((size_t)(b * NHh + hH) * Ss + srow) * stride + d;
                    *(__half2*)(D + o) = __floats2half2_rn(acc[mi][n8][rr*2], acc[mi][n8][rr*2+1]);
                }
            }
    }
}

// ================= G5: out = at_h @ wo^T (fp32 out) =================
__global__ void __launch_bounds__(256, 2) gemm_c(
    const __half* __restrict__ at, const __half* __restrict__ wo,
    float* __restrict__ out) {
    extern __shared__ char sm[];
    uint32_t sbase = smem_u32(sm);
    int tid = threadIdx.x, lane = tid & 31, wid = tid >> 5;
    int warpM = wid & 3, warpN = wid >> 2;
    int row0 = blockIdx.y * 128, col0 = blockIdx.x * 128;

    float acc[2][8][4];
    gemm_mainloop(at + (size_t)row0 * HID, wo + (size_t)col0 * HID, HID,
                  sbase, acc, tid, lane, warpM, warpN);

    int g = lane >> 2, t = lane & 3;
#pragma unroll
    for (int mi = 0; mi < 2; mi++)
#pragma unroll
        for (int n8 = 0; n8 < 8; n8++) {
            int col = col0 + warpN * 64 + n8 * 8 + t * 2;
            int r0 = row0 + warpM * 32 + mi * 16 + g;
            float* p0 = out + (size_t)r0 * HID + col;
            p0[0] = acc[mi][n8][0]; p0[1] = acc[mi][n8][1];
            float* p1 = p0 + (size_t)8 * HID;
            p1[0] = acc[mi][n8][2]; p1[1] = acc[mi][n8][3];
        }
}

// ================= conversion / transpose kernels =================
__global__ void convert_h(const float* __restrict__ x, __half* __restrict__ h, size_t n) {
    size_t i = ((size_t)blockIdx.x * 256 + threadIdx.x) * 4;
    if (i >= n) return;
    float4 v = *(const float4*)(x + i);
    *(__half2*)(h + i)     = __floats2half2_rn(v.x, v.y);
    *(__half2*)(h + i + 2) = __floats2half2_rn(v.z, v.w);
}

__global__ void transpose_h(const float* __restrict__ W, __half* __restrict__ Th, int K, int N) {
    __shared__ float tile[32][33];
    int n0 = blockIdx.x * 32, k0 = blockIdx.y * 32;
    int tx = threadIdx.x, ty = threadIdx.y;
#pragma unroll
    for (int i = 0; i < 4; i++) {
        int k = k0 + ty + i * 8, n = n0 + tx;
        tile[ty + i * 8][tx] = (n < N) ? W[(size_t)k * N + n] : 0.f;
    }
    __syncthreads();
#pragma unroll
    for (int i = 0; i < 4; i++) {
        int n = n0 + ty + i * 8;
        Th[(size_t)n * K + k0 + tx] = __float2half(tile[tx][ty + i * 8]);
    }
}

// ================= merged rmsnorm + kv_split =================
__global__ void norm_fused(const float* __restrict__ qc, const float* __restrict__ qw,
                           const float* __restrict__ kvt, const float* __restrict__ kvw,
                           const int* __restrict__ pos,
                           __half* __restrict__ qch, __half* __restrict__ kvch,
                           __half* __restrict__ kfh) {
    __shared__ float red[256];
    __shared__ float rop[64];
    int tid = threadIdx.x;
    if (blockIdx.x < ROWS) {
        int row = blockIdx.x;
        const float* r = qc + (size_t)row * QLORA;
        float ss = 0.f;
        for (int i = tid; i < QLORA; i += 256) { float v = r[i]; ss += v * v; }
        red[tid] = ss; __syncthreads();
        for (int s = 128; s > 0; s >>= 1) { if (tid < s) red[tid] += red[tid + s]; __syncthreads(); }
        float scale = rsqrtf(red[0] / (float)QLORA + 1e-6f);
        for (int i = tid; i < QLORA; i += 256)
            qch[(size_t)row * QLORA + i] = __float2half(r[i] * scale * qw[i]);
    } else {
        int row = blockIdx.x - ROWS;
        const float* r = kvt + (size_t)row * (KVLORA + ROPED);
        float ss = 0.f;
        for (int i = tid; i < KVLORA; i += 256) { float v = r[i]; ss += v * v; }
        red[tid] = ss; __syncthreads();
        for (int s = 128; s > 0; s >>= 1) { if (tid < s) red[tid] += red[tid + s]; __syncthreads(); }
        float scale = rsqrtf(red[0] / (float)KVLORA + 1e-6f);
        for (int i = tid; i < KVLORA; i += 256)
            kvch[(size_t)row * KVLORA + i] = __float2half(r[i] * scale * kvw[i]);
        if (tid < 32) {
            float p = (float)pos[row];
            float inv_freq = __expf(-(float)tid * (LN10K / 32.f));
            float ang = p * inv_freq;
            float c, s;
            __sincosf(ang, &s, &c);
            float x1 = r[KVLORA + tid];
            float x2 = r[KVLORA + 32 + tid];
            rop[tid]      = x1 * c - x2 * s;
            rop[tid + 32] = x2 * c + x1 * s;
        }
        __syncthreads();
        int b = row >> 11, srow = row & 2047;
        for (int e = tid; e < NHh * ROPED; e += 256) {
            int h = e >> 6, d = e & 63;
            size_t o = ((size_t)(b * NHh + h) * Ss + srow) * QKD + NOPE + d;
            kfh[o] = __float2half(rop[d]);
        }
    }
}

// ================= fp16 tensor-core flash attention =================
#define FQ_PITCH 400
#define FV_PITCH 272
#define FQ_SZ    (128*FQ_PITCH)           // 51200
#define FK_SZ    (32*FQ_PITCH)            // 12800
#define FV_SZ    (32*FV_PITCH)            // 8704
#define F_OFF_K  FQ_SZ
#define F_OFF_V  (F_OFF_K + 2*FK_SZ)      // 76800
#define FLASH_SMEM (F_OFF_V + 2*FV_SZ)    // 94208

__global__ void __launch_bounds__(256, 2) flash_mma(
    const __half* __restrict__ qh, const __half* __restrict__ kh,
    const __half* __restrict__ vh, __half* __restrict__ oh) {
    extern __shared__ char sm[];
    uint32_t sb = smem_u32(sm);

    int qt = (gridDim.x - 1) - blockIdx.x;
    int h = blockIdx.y, b = blockIdx.z;
    int q0 = qt * 128;
    int tid = threadIdx.x, lane = tid & 31, w = tid >> 5;
    int bh = b * NHh + h;

    const __half* qhb = qh + ((size_t)bh * Ss + q0) * QKD;
    const __half* khb = kh + (size_t)bh * Ss * QKD;
    const __half* vhb = vh + (size_t)bh * Ss * VDIM;

#pragma unroll
    for (int i = 0; i < 12; i++) {
        int e = tid + i * 256;
        int r = e / 24, c = e % 24;
        CP_ASYNC16(sb + r * FQ_PITCH + c * 16, qhb + (size_t)r * QKD + c * 8);
    }

    auto load_kv = [&](int kt, int s) {
        int k0 = kt * 32;
        uint32_t kst = sb + F_OFF_K + s * FK_SZ;
        uint32_t vst = sb + F_OFF_V + s * FV_SZ;
#pragma unroll
        for (int i = 0; i < 3; i++) {
            int e = tid + i * 256;
            int r = e / 24, c = e % 24;
            CP_ASYNC16(kst + r * FQ_PITCH + c * 16, khb + (size_t)(k0 + r) * QKD + c * 8);
        }
        {
            int e = tid * 2;
            int r = e >> 4, c = e & 15;
            CP_ASYNC16(vst + r * FV_PITCH + c * 16, vhb + (size_t)(k0 + r) * VDIM + c * 8);
            CP_ASYNC16(vst + r * FV_PITCH + (c + 1) * 16, vhb + (size_t)(k0 + r) * VDIM + (c + 1) * 8);
        }
    };

    load_kv(0, 0);
    CP_COMMIT();

    int a_r = w * 16 + (lane & 15);
    int a_c8 = (lane >> 4) << 3;
    int b_r = ((lane >> 4) << 3) + (lane & 7);
    int b_c8 = ((lane >> 3) & 1) << 3;
    int vt_r = lane & 15;
    int vt_c8 = (lane >> 4) << 3;

    int g = lane >> 2, t4 = lane & 3;

    float m0 = -INFINITY, m1 = -INFINITY, l0 = 0.f, l1 = 0.f;
    float O[16][4];
#pragma unroll
    for (int j = 0; j < 16; j++)
#pragma unroll
        for (int k = 0; k < 4; k++) O[j][k] = 0.f;

    int qrow0 = q0 + w * 16 + g;
    int qrow1 = qrow0 + 8;

    int nkt = (q0 + 128) >> 5;

    for (int kt = 0; kt < nkt; kt++) {
        int s = kt & 1;
        if (kt + 1 < nkt) { load_kv(kt + 1, s ^ 1); CP_COMMIT(); CP_WAIT1(); }
        else              { CP_WAIT0(); }
        __syncthreads();

        uint32_t kst = sb + F_OFF_K + s * FK_SZ;
        uint32_t vst = sb + F_OFF_V + s * FV_SZ;
        int k0 = kt * 32;

        float sc[4][4];
#pragma unroll
        for (int j = 0; j < 4; j++)
#pragma unroll
            for (int k = 0; k < 4; k++) sc[j][k] = 0.f;

#pragma unroll
        for (int kk = 0; kk < 12; kk++) {
            uint32_t ah[4];
            LDSM4(ah, sb + (uint32_t)(a_r * FQ_PITCH + (kk * 16 + a_c8) * 2));
#pragma unroll
            for (int nb = 0; nb < 2; nb++) {
                uint32_t bhf[4];
                LDSM4(bhf, kst + (uint32_t)((nb * 16 + b_r) * FQ_PITCH + (kk * 16 + b_c8) * 2));
                MMA16816(sc[2*nb],   ah, bhf[0], bhf[1]);
                MMA16816(sc[2*nb+1], ah, bhf[2], bhf[3]);
            }
        }

        if (k0 + 31 > q0) {
#pragma unroll
            for (int j = 0; j < 4; j++) {
                int col = k0 + j * 8 + t4 * 2;
                if (col     > qrow0) sc[j][0] = -INFINITY;
                if (col + 1 > qrow0) sc[j][1] = -INFINITY;
                if (col     > qrow1) sc[j][2] = -INFINITY;
                if (col + 1 > qrow1) sc[j][3] = -INFINITY;
            }
        }

        float rm0 = -INFINITY, rm1 = -INFINITY;
#pragma unroll
        for (int j = 0; j < 4; j++) {
            rm0 = fmaxf(rm0, fmaxf(sc[j][0], sc[j][1]));
            rm1 = fmaxf(rm1, fmaxf(sc[j][2], sc[j][3]));
        }
        rm0 = fmaxf(rm0, __shfl_xor_sync(0xffffffffu, rm0, 1));
        rm0 = fmaxf(rm0, __shfl_xor_sync(0xffffffffu, rm0, 2));
        rm1 = fmaxf(rm1, __shfl_xor_sync(0xffffffffu, rm1, 1));
        rm1 = fmaxf(rm1, __shfl_xor_sync(0xffffffffu, rm1, 2));
        float nm0 = fmaxf(m0, rm0), nm1 = fmaxf(m1, rm1);
        float rs0 = 0.f, rs1 = 0.f;
#pragma unroll
        for (int j = 0; j < 4; j++) {
            sc[j][0] = __expf(sc[j][0] - nm0);
            sc[j][1] = __expf(sc[j][1] - nm0);
            sc[j][2] = __expf(sc[j][2] - nm1);
            sc[j][3] = __expf(sc[j][3] - nm1);
            rs0 += sc[j][0] + sc[j][1];
            rs1 += sc[j][2] + sc[j][3];
        }
        rs0 += __shfl_xor_sync(0xffffffffu, rs0, 1);
        rs0 += __shfl_xor_sync(0xffffffffu, rs0, 2);
        rs1 += __shfl_xor_sync(0xffffffffu, rs1, 1);
        rs1 += __shfl_xor_sync(0xffffffffu, rs1, 2);
        float al0 = __expf(m0 - nm0), al1 = __expf(m1 - nm1);
        l0 = l0 * al0 + rs0; l1 = l1 * al1 + rs1;
        m0 = nm0; m1 = nm1;
#pragma unroll
        for (int j = 0; j < 16; j++) {
            O[j][0] *= al0; O[j][1] *= al0;
            O[j][2] *= al1; O[j][3] *= al1;
        }

        uint32_t ph2[4][2];
#pragma unroll
        for (int j = 0; j < 4; j++) {
            __half2 p01 = __floats2half2_rn(sc[j][0], sc[j][1]);
            __half2 p23 = __floats2half2_rn(sc[j][2], sc[j][3]);
            ph2[j][0] = *(uint32_t*)&p01;
            ph2[j][1] = *(uint32_t*)&p23;
        }

#pragma unroll
        for (int kk = 0; kk < 2; kk++) {
            uint32_t ah[4] = { ph2[2*kk][0], ph2[2*kk][1], ph2[2*kk+1][0], ph2[2*kk+1][1] };
#pragma unroll
            for (int j2 = 0; j2 < 8; j2++) {
                uint32_t vhf[4];
                LDSM4T(vhf, vst + (uint32_t)((kk * 16 + vt_r) * FV_PITCH + (j2 * 16 + vt_c8) * 2));
                MMA16816(O[2*j2],   ah, vhf[0], vhf[1]);
                MMA16816(O[2*j2+1], ah, vhf[2], vhf[3]);
            }
        }
        __syncthreads();
    }

    float inv0 = 1.f / l0, inv1 = 1.f / l1;
    size_t ob0 = ((size_t)(b * Ss + qrow0)) * (NHh * VDIM) + h * VDIM;
    size_t ob1 = ((size_t)(b * Ss + qrow1)) * (NHh * VDIM) + h * VDIM;
#pragma unroll
    for (int j = 0; j < 16; j++) {
        int d = j * 8 + t4 * 2;
        *(__half2*)(oh + ob0 + d) = __floats2half2_rn(O[j][0] * inv0, O[j][1] * inv0);
        *(__half2*)(oh + ob1 + d) = __floats2half2_rn(O[j][2] * inv1, O[j][3] * inv1);
    }
}

// ================= launch =================
extern "C" void kernel_launch(void* const* d_in, const int* in_sizes, int n_in,
                              void* d_out, int out_size) {
    const float* hs     = (const float*)d_in[0];
    const int*   pos    = (const int*)  d_in[1];
    const float* w_q_a  = (const float*)d_in[3];
    const float* q_ln   = (const float*)d_in[4];
    const float* w_q_b  = (const float*)d_in[5];
    const float* w_kv_a = (const float*)d_in[6];
    const float* kv_ln  = (const float*)d_in[7];
    const float* w_kv_b = (const float*)d_in[8];
    const float* w_o    = (const float*)d_in[9];
    float* out = (float*)d_out;

    float *qc, *kvt;
    cudaGetSymbolAddress((void**)&qc,  g_qc);
    cudaGetSymbolAddress((void**)&kvt, g_kvt);

    __half *hs_h,*qc_h,*kvc_h,*at_h;
    __half *wqa_h,*wqb_h,*wkva_h,*wkvb_h,*wo_h;
    __half *qfh,*kfh,*vfh;
    cudaGetSymbolAddress((void**)&hs_h,  g_hs_h);
    cudaGetSymbolAddress((void**)&qc_h,  g_qc_h);
    cudaGetSymbolAddress((void**)&kvc_h, g_kvc_h);
    cudaGetSymbolAddress((void**)&at_h,  g_at_h);
    cudaGetSymbolAddress((void**)&wqa_h, g_wqa_h);
    cudaGetSymbolAddress((void**)&wqb_h, g_wqb_h);
    cudaGetSymbolAddress((void**)&wkva_h,g_wkva_h);
    cudaGetSymbolAddress((void**)&wkvb_h,g_wkvb_h);
    cudaGetSymbolAddress((void**)&wo_h,  g_wo_h);
    cudaGetSymbolAddress((void**)&qfh,   g_qfh);
    cudaGetSymbolAddress((void**)&kfh,   g_kfh);
    cudaGetSymbolAddress((void**)&vfh,   g_vfh);

    cudaFuncSetAttribute(gemm_a, cudaFuncAttributeMaxDynamicSharedMemorySize, GEMM_SMEM);
    cudaFuncSetAttribute(gemm_b, cudaFuncAttributeMaxDynamicSharedMemorySize, GEMM_SMEM);
    cudaFuncSetAttribute(gemm_c, cudaFuncAttributeMaxDynamicSharedMemorySize, GEMM_SMEM);
    cudaFuncSetAttribute(flash_mma, cudaFuncAttributeMaxDynamicSharedMemorySize, FLASH_SMEM);

    dim3 tb(32, 8);

    // weight prep
    transpose_h<<<dim3(QLORA/32, HID/32), tb>>>(w_q_a, wqa_h, HID, QLORA);
    transpose_h<<<dim3((NHh*QKD)/32, QLORA/32), tb>>>(w_q_b, wqb_h, QLORA, NHh*QKD);
    transpose_h<<<dim3(WKVA_NPAD/32, HID/32), tb>>>(w_kv_a, wkva_h, HID, KVLORA+ROPED);
    transpose_h<<<dim3((NHh*(NOPE+VDIM))/32, KVLORA/32), tb>>>(w_kv_b, wkvb_h, KVLORA, NHh*(NOPE+VDIM));
    transpose_h<<<dim3(HID/32, (NHh*VDIM)/32), tb>>>(w_o, wo_h, NHh*VDIM, HID);
    convert_h<<<(ROWS*(size_t)HID/4 + 255)/256, 256>>>(hs, hs_h, (size_t)ROWS*HID);

    // merged G1+G3
    gemm_a<<<dim3(12 + WKVA_NPAD/128, ROWS/128), 256, GEMM_SMEM>>>(
        hs_h, wqa_h, wkva_h, qc, kvt);

    // merged rmsnorm + kv_split (+ k-rope into kfh)
    norm_fused<<<2*ROWS, 256>>>(qc, q_ln, kvt, kv_ln, pos, qc_h, kvc_h, kfh);

    // merged G2 (rope epilogue -> qfh) + G4 (scatter -> kfh/vfh)
    gemm_b<<<dim3(24 + 32, ROWS/128), 256, GEMM_SMEM>>>(
        qc_h, wqb_h, kvc_h, wkvb_h, pos, qfh, kfh, vfh);

    // attention
    flash_mma<<<dim3(Ss/128, NHh, Bb), 256, FLASH_SMEM>>>(qfh, kfh, vfh, at_h);

    // G5
    gemm_c<<<dim3(HID/128, ROWS/128), 256, GEMM_SMEM>>>(at_h, wo_h, out);
}

// round 9
// speedup vs baseline: 2.7206x; 1.0162x over previous
#include <cuda_runtime.h>
#include <cuda_fp16.h>
#include <math.h>
#include <cstdint>

// ---------------- problem constants ----------------
#define Bb   2
#define Ss   2048
#define HID  2048
#define NHh  16
#define QLORA 1536
#define KVLORA 512
#define NOPE 128
#define ROPED 64
#define VDIM 128
#define QKD  192
#define ROWS (Bb*Ss)          // 4096
#define WKVA_NPAD 640
#define SCALEF 0.07216878364870322f
#define LN10K  9.210340371976184f

// ---------------- fp32 scratch ----------------
__device__ float g_qc   [(size_t)ROWS * QLORA];
__device__ float g_kvt  [(size_t)ROWS * (KVLORA+ROPED)];

// ---------------- fp16 activations ----------------
__device__ __half g_hs_h [(size_t)ROWS*HID];
__device__ __half g_qc_h [(size_t)ROWS*QLORA];
__device__ __half g_kvc_h[(size_t)ROWS*KVLORA];
__device__ __half g_at_h [(size_t)ROWS*NHh*VDIM];

// ---------------- fp16 transposed weights [N,K] ----------------
__device__ __half g_wqa_h [(size_t)QLORA*HID];
__device__ __half g_wqb_h [(size_t)(NHh*QKD)*QLORA];
__device__ __half g_wkva_h[(size_t)WKVA_NPAD*HID];
__device__ __half g_wkvb_h[(size_t)(NHh*(NOPE+VDIM))*KVLORA];
__device__ __half g_wo_h  [(size_t)HID*(NHh*VDIM)];

// ---------------- flash fp16 buffers, [b,h,s,d] ----------------
__device__ __half g_qfh[(size_t)ROWS*NHh*QKD];
__device__ __half g_kfh[(size_t)ROWS*NHh*QKD];
__device__ __half g_vfh[(size_t)ROWS*NHh*VDIM];

// ================= helpers =================
__device__ __forceinline__ uint32_t smem_u32(const void* p) {
    uint32_t a;
    asm("{ .reg .u64 t; cvta.to.shared.u64 t, %1; cvt.u32.u64 %0, t; }" : "=r"(a) : "l"(p));
    return a;
}

#define LDSM4(r, a) asm volatile( \
    "ldmatrix.sync.aligned.m8n8.x4.shared.b16 {%0,%1,%2,%3}, [%4];" \
    : "=r"((r)[0]),"=r"((r)[1]),"=r"((r)[2]),"=r"((r)[3]) : "r"(a))

#define LDSM4T(r, a) asm volatile( \
    "ldmatrix.sync.aligned.m8n8.x4.trans.shared.b16 {%0,%1,%2,%3}, [%4];" \
    : "=r"((r)[0]),"=r"((r)[1]),"=r"((r)[2]),"=r"((r)[3]) : "r"(a))

#define MMA16816(d, a, b0v, b1v) asm volatile( \
    "mma.sync.aligned.m16n8k16.row.col.f32.f16.f16.f32 " \
    "{%0,%1,%2,%3},{%4,%5,%6,%7},{%8,%9},{%0,%1,%2,%3};" \
    : "+f"((d)[0]),"+f"((d)[1]),"+f"((d)[2]),"+f"((d)[3]) \
    : "r"((a)[0]),"r"((a)[1]),"r"((a)[2]),"r"((a)[3]), "r"(b0v),"r"(b1v))

#define CP_ASYNC16(sa, ga) asm volatile( \
    "cp.async.cg.shared.global [%0], [%1], 16;" :: "r"(sa), "l"(ga))
#define CP_COMMIT() asm volatile("cp.async.commit_group;" ::: "memory")
#define CP_WAIT1()  asm volatile("cp.async.wait_group 1;" ::: "memory")
#define CP_WAIT0()  asm volatile("cp.async.wait_group 0;" ::: "memory")

// ================= fp16 HMMA GEMM mainloop (shared) =================
#define BK 32
#define PITCH 40
#define TILE_B (128*PITCH*2)          // 10240
#define STAGE_B (2*TILE_B)            // 20480
#define NSTAGE 3
#define GEMM_SMEM (NSTAGE*STAGE_B)    // 61440

__device__ __forceinline__ void gemm_mainloop(
    const __half* __restrict__ gA, const __half* __restrict__ gB, int K,
    uint32_t sbase, float acc[2][8][4],
    int tid, int lane, int warpM, int warpN) {

    auto issue_loads = [&](int c, int s) {
        int k0 = c * BK;
        uint32_t st = sbase + s * STAGE_B;
#pragma unroll
        for (int j = 0; j < 2; j++) {
            int seg = tid + j * 256;
            int r = seg >> 2, cc = seg & 3;
            CP_ASYNC16(st + r * (PITCH * 2) + cc * 16, gA + (size_t)r * K + k0 + cc * 8);
            CP_ASYNC16(st + TILE_B + r * (PITCH * 2) + cc * 16, gB + (size_t)r * K + k0 + cc * 8);
        }
        CP_COMMIT();
    };

#pragma unroll
    for (int i = 0; i < 2; i++)
#pragma unroll
        for (int j = 0; j < 8; j++)
#pragma unroll
            for (int k = 0; k < 4; k++) acc[i][j][k] = 0.f;

    int a_r = warpM * 32 + (lane & 15);
    int a_c8 = (lane >> 4) << 3;
    int b_r = warpN * 64 + ((lane >> 4) << 3) + (lane & 7);
    int b_c8 = ((lane >> 3) & 1) << 3;

    auto compute = [&](int s) {
        uint32_t st = sbase + s * STAGE_B;
#pragma unroll
        for (int ki = 0; ki < 2; ki++) {
            uint32_t ah[2][4];
#pragma unroll
            for (int mi = 0; mi < 2; mi++) {
                uint32_t off = (uint32_t)((a_r + mi * 16) * (PITCH * 2) + (ki * 16 + a_c8) * 2);
                LDSM4(ah[mi], st + off);
            }
            uint32_t bh[4][4];
#pragma unroll
            for (int nb = 0; nb < 4; nb++) {
                uint32_t off = (uint32_t)((b_r + nb * 16) * (PITCH * 2) + (ki * 16 + b_c8) * 2);
                LDSM4(bh[nb], st + TILE_B + off);
            }
#pragma unroll
            for (int mi = 0; mi < 2; mi++)
#pragma unroll
                for (int nb = 0; nb < 4; nb++) {
                    MMA16816(acc[mi][2*nb],   ah[mi], bh[nb][0], bh[nb][1]);
                    MMA16816(acc[mi][2*nb+1], ah[mi], bh[nb][2], bh[nb][3]);
                }
        }
    };

    int nc = K / BK;
    issue_loads(0, 0);
    issue_loads(1, 1);
    for (int c = 0; c < nc; c++) {
        int s = c % NSTAGE;
        if (c + 1 < nc) { CP_WAIT1(); } else { CP_WAIT0(); }
        __syncthreads();
        if (c + 2 < nc) issue_loads(c + 2, (c + 2) % NSTAGE);
        compute(s);
    }
}

// ================= merged G1+G3 =================
__global__ void __launch_bounds__(256, 2) gemm_a(
    const __half* __restrict__ hs, const __half* __restrict__ wqa,
    const __half* __restrict__ wkva,
    float* __restrict__ qc, float* __restrict__ kvt) {
    extern __shared__ char sm[];
    uint32_t sbase = smem_u32(sm);
    int tid = threadIdx.x, lane = tid & 31, wid = tid >> 5;
    int warpM = wid & 3, warpN = wid >> 2;
    int row0 = blockIdx.y * 128;
    int bx = blockIdx.x;

    const __half* B;
    float* C; int cN, col0, Nlim;
    if (bx < 12) { col0 = bx * 128;        B = wqa  + (size_t)col0 * HID; C = qc;  cN = QLORA; Nlim = QLORA; }
    else         { col0 = (bx - 12) * 128; B = wkva + (size_t)col0 * HID; C = kvt; cN = KVLORA+ROPED; Nlim = KVLORA+ROPED; }

    float acc[2][8][4];
    gemm_mainloop(hs + (size_t)row0 * HID, B, HID, sbase, acc, tid, lane, warpM, warpN);

    int g = lane >> 2, t = lane & 3;
#pragma unroll
    for (int mi = 0; mi < 2; mi++)
#pragma unroll
        for (int n8 = 0; n8 < 8; n8++) {
            int col = col0 + warpN * 64 + n8 * 8 + t * 2;
            if (col < Nlim) {
                int r0 = row0 + warpM * 32 + mi * 16 + g;
                float* p0 = C + (size_t)r0 * cN + col;
                p0[0] = acc[mi][n8][0]; p0[1] = acc[mi][n8][1];
                float* p1 = p0 + (size_t)8 * cN;
                p1[0] = acc[mi][n8][2]; p1[1] = acc[mi][n8][3];
            }
        }
}

// ================= merged G2+G4 =================
__global__ void __launch_bounds__(256, 2) gemm_b(
    const __half* __restrict__ qch, const __half* __restrict__ wqb,
    const __half* __restrict__ kvch, const __half* __restrict__ wkvb,
    const int* __restrict__ pos,
    __half* __restrict__ qfh, __half* __restrict__ kfh, __half* __restrict__ vfh) {
    extern __shared__ char sm[];
    uint32_t sbase = smem_u32(sm);
    int tid = threadIdx.x, lane = tid & 31, wid = tid >> 5;
    int warpM = wid & 3, warpN = wid >> 2;
    int row0 = blockIdx.y * 128;
    int bx = blockIdx.x;
    int g = lane >> 2, t4 = lane & 3;

    if (bx < 24) {
        int col0 = bx * 128;
        float acc[2][8][4];
        gemm_mainloop(qch + (size_t)row0 * QLORA, wqb + (size_t)col0 * QLORA, QLORA,
                      sbase, acc, tid, lane, warpM, warpN);

        int colw = col0 + warpN * 64;
        int hH = colw / 192;
        int dbase = colw % 192;
        if (dbase != 128) {
#pragma unroll
            for (int mi = 0; mi < 2; mi++)
#pragma unroll
                for (int rr = 0; rr < 2; rr++) {
                    int row = row0 + warpM * 32 + mi * 16 + g + rr * 8;
                    int b = row >> 11, srow = row & 2047;
                    size_t obase = ((size_t)(b * NHh + hH) * Ss + srow) * QKD;
#pragma unroll
                    for (int n8 = 0; n8 < 8; n8++) {
                        int d = dbase + n8 * 8 + t4 * 2;
                        *(__half2*)(qfh + obase + d) = __floats2half2_rn(
                            acc[mi][n8][rr*2] * SCALEF, acc[mi][n8][rr*2+1] * SCALEF);
                    }
                }
        } else {
#pragma unroll
            for (int mi = 0; mi < 2; mi++)
#pragma unroll
                for (int rr = 0; rr < 2; rr++) {
                    int row = row0 + warpM * 32 + mi * 16 + g + rr * 8;
                    int b = row >> 11, srow = row & 2047;
                    float p = (float)pos[b * Ss + srow];
                    size_t obase = ((size_t)(b * NHh + hH) * Ss + srow) * QKD;
#pragma unroll
                    for (int n8 = 0; n8 < 4; n8++) {
                        int j0 = n8 * 8 + t4 * 2;
                        float if0 = __expf(-(float)j0 * (LN10K / 32.f));
                        float if1 = __expf(-(float)(j0 + 1) * (LN10K / 32.f));
                        float s0, c0, s1, c1;
                        __sincosf(p * if0, &s0, &c0);
                        __sincosf(p * if1, &s1, &c1);
                        float x1a = acc[mi][n8][rr*2],   x2a = acc[mi][n8+4][rr*2];
                        float x1b = acc[mi][n8][rr*2+1], x2b = acc[mi][n8+4][rr*2+1];
                        *(__half2*)(qfh + obase + 128 + j0) = __floats2half2_rn(
                            (x1a * c0 - x2a * s0) * SCALEF, (x1b * c1 - x2b * s1) * SCALEF);
                        *(__half2*)(qfh + obase + 160 + j0) = __floats2half2_rn(
                            (x2a * c0 + x1a * s0) * SCALEF, (x2b * c1 + x1b * s1) * SCALEF);
                    }
                }
        }
    } else {
        int col0 = (bx - 24) * 128;
        float acc[2][8][4];
        gemm_mainloop(kvch + (size_t)row0 * KVLORA, wkvb + (size_t)col0 * KVLORA, KVLORA,
                      sbase, acc, tid, lane, warpM, warpN);

        int hH = col0 >> 8;
        int isV = (col0 >> 7) & 1;
        __half* D = isV ? vfh : kfh;
        int stride = isV ? VDIM : QKD;
#pragma unroll
        for (int mi = 0; mi < 2; mi++)
#pragma unroll
            for (int n8 = 0; n8 < 8; n8++) {
                int col = col0 + warpN * 64 + n8 * 8 + t4 * 2;
                int d = col & 127;
#pragma unroll
                for (int rr = 0; rr < 2; rr++) {
                    int r0 = row0 + warpM * 32 + mi * 16 + g + rr * 8;
                    int b = r0 >> 11, srow = r0 & 2047;
                    size_t o = ((size_t)(b * NHh + hH) * Ss + srow) * stride + d;
                    *(__half2*)(D + o) = __floats2half2_rn(acc[mi][n8][rr*2], acc[mi][n8][rr*2+1]);
                }
            }
    }
}

// ================= G5 =================
__global__ void __launch_bounds__(256, 2) gemm_c(
    const __half* __restrict__ at, const __half* __restrict__ wo,
    float* __restrict__ out) {
    extern __shared__ char sm[];
    uint32_t sbase = smem_u32(sm);
    int tid = threadIdx.x, lane = tid & 31, wid = tid >> 5;
    int warpM = wid & 3, warpN = wid >> 2;
    int row0 = blockIdx.y * 128, col0 = blockIdx.x * 128;

    float acc[2][8][4];
    gemm_mainloop(at + (size_t)row0 * HID, wo + (size_t)col0 * HID, HID,
                  sbase, acc, tid, lane, warpM, warpN);

    int g = lane >> 2, t = lane & 3;
#pragma unroll
    for (int mi = 0; mi < 2; mi++)
#pragma unroll
        for (int n8 = 0; n8 < 8; n8++) {
            int col = col0 + warpN * 64 + n8 * 8 + t * 2;
            int r0 = row0 + warpM * 32 + mi * 16 + g;
            float* p0 = out + (size_t)r0 * HID + col;
            p0[0] = acc[mi][n8][0]; p0[1] = acc[mi][n8][1];
            float* p1 = p0 + (size_t)8 * HID;
            p1[0] = acc[mi][n8][2]; p1[1] = acc[mi][n8][3];
        }
}

// ================= merged prep kernels =================
__device__ __forceinline__ void do_transpose(
    const float* __restrict__ W, __half* __restrict__ Th,
    int K, int srcN, int colTiles, int tile, int tid) {
    __shared__ float t[32][33];
    int n0 = (tile % colTiles) * 32, k0 = (tile / colTiles) * 32;
    int tx = tid & 31, ty = tid >> 5;
#pragma unroll
    for (int i = 0; i < 4; i++) {
        int k = k0 + ty + i * 8, n = n0 + tx;
        t[ty + i * 8][tx] = (n < srcN) ? W[(size_t)k * srcN + n] : 0.f;
    }
    __syncthreads();
#pragma unroll
    for (int i = 0; i < 4; i++) {
        int n = n0 + ty + i * 8;
        Th[(size_t)n * K + k0 + tx] = __float2half(t[tx][ty + i * 8]);
    }
}

// hs convert (4096 blocks) + wqa transpose (3072) + wkva transpose (1280)
__global__ void prep_main(const float* __restrict__ hs, __half* __restrict__ hsh,
                          const float* __restrict__ wqa, __half* __restrict__ wqah,
                          const float* __restrict__ wkva, __half* __restrict__ wkvah) {
    int bx = blockIdx.x, tid = threadIdx.x;
    if (bx < 4096) {
        size_t i = ((size_t)bx * 256 + tid) * 8;
        float4 v0 = *(const float4*)(hs + i);
        float4 v1 = *(const float4*)(hs + i + 4);
        *(__half2*)(hsh + i)     = __floats2half2_rn(v0.x, v0.y);
        *(__half2*)(hsh + i + 2) = __floats2half2_rn(v0.z, v0.w);
        *(__half2*)(hsh + i + 4) = __floats2half2_rn(v1.x, v1.y);
        *(__half2*)(hsh + i + 6) = __floats2half2_rn(v1.z, v1.w);
    } else if (bx < 4096 + 3072) {
        do_transpose(wqa, wqah, HID, QLORA, QLORA/32, bx - 4096, tid);
    } else {
        do_transpose(wkva, wkvah, HID, KVLORA+ROPED, WKVA_NPAD/32, bx - 7168, tid);
    }
}

// wqb (4608) + wkvb (2048) + wo (4096)
__global__ void prep_aux(const float* __restrict__ wqb, __half* __restrict__ wqbh,
                         const float* __restrict__ wkvb, __half* __restrict__ wkvbh,
                         const float* __restrict__ wo, __half* __restrict__ woh) {
    int bx = blockIdx.x, tid = threadIdx.x;
    if (bx < 4608) {
        do_transpose(wqb, wqbh, QLORA, NHh*QKD, (NHh*QKD)/32, bx, tid);
    } else if (bx < 4608 + 2048) {
        do_transpose(wkvb, wkvbh, KVLORA, NHh*(NOPE+VDIM), (NHh*(NOPE+VDIM))/32, bx - 4608, tid);
    } else {
        do_transpose(wo, woh, NHh*VDIM, HID, HID/32, bx - 6656, tid);
    }
}

// ================= merged rmsnorm + kv_split =================
__global__ void norm_fused(const float* __restrict__ qc, const float* __restrict__ qw,
                           const float* __restrict__ kvt, const float* __restrict__ kvw,
                           const int* __restrict__ pos,
                           __half* __restrict__ qch, __half* __restrict__ kvch,
                           __half* __restrict__ kfh) {
    __shared__ float red[256];
    __shared__ float rop[64];
    int tid = threadIdx.x;
    if (blockIdx.x < ROWS) {
        int row = blockIdx.x;
        const float* r = qc + (size_t)row * QLORA;
        float ss = 0.f;
        for (int i = tid; i < QLORA; i += 256) { float v = r[i]; ss += v * v; }
        red[tid] = ss; __syncthreads();
        for (int s = 128; s > 0; s >>= 1) { if (tid < s) red[tid] += red[tid + s]; __syncthreads(); }
        float scale = rsqrtf(red[0] / (float)QLORA + 1e-6f);
        for (int i = tid; i < QLORA; i += 256)
            qch[(size_t)row * QLORA + i] = __float2half(r[i] * scale * qw[i]);
    } else {
        int row = blockIdx.x - ROWS;
        const float* r = kvt + (size_t)row * (KVLORA + ROPED);
        float ss = 0.f;
        for (int i = tid; i < KVLORA; i += 256) { float v = r[i]; ss += v * v; }
        red[tid] = ss; __syncthreads();
        for (int s = 128; s > 0; s >>= 1) { if (tid < s) red[tid] += red[tid + s]; __syncthreads(); }
        float scale = rsqrtf(red[0] / (float)KVLORA + 1e-6f);
        for (int i = tid; i < KVLORA; i += 256)
            kvch[(size_t)row * KVLORA + i] = __float2half(r[i] * scale * kvw[i]);
        if (tid < 32) {
            float p = (float)pos[row];
            float inv_freq = __expf(-(float)tid * (LN10K / 32.f));
            float ang = p * inv_freq;
            float c, s;
            __sincosf(ang, &s, &c);
            float x1 = r[KVLORA + tid];
            float x2 = r[KVLORA + 32 + tid];
            rop[tid]      = x1 * c - x2 * s;
            rop[tid + 32] = x2 * c + x1 * s;
        }
        __syncthreads();
        int b = row >> 11, srow = row & 2047;
        for (int e = tid; e < NHh * ROPED; e += 256) {
            int h = e >> 6, d = e & 63;
            size_t o = ((size_t)(b * NHh + h) * Ss + srow) * QKD + NOPE + d;
            kfh[o] = __float2half(rop[d]);
        }
    }
}

// ================= fp16 tensor-core flash attention =================
#define FQ_PITCH 400
#define FV_PITCH 272
#define FQ_SZ    (128*FQ_PITCH)
#define FK_SZ    (32*FQ_PITCH)
#define FV_SZ    (32*FV_PITCH)
#define F_OFF_K  FQ_SZ
#define F_OFF_V  (F_OFF_K + 2*FK_SZ)
#define FLASH_SMEM (F_OFF_V + 2*FV_SZ)    // 94208

__global__ void __launch_bounds__(256, 2) flash_mma(
    const __half* __restrict__ qh, const __half* __restrict__ kh,
    const __half* __restrict__ vh, __half* __restrict__ oh) {
    extern __shared__ char sm[];
    uint32_t sb = smem_u32(sm);

    int qt = (gridDim.x - 1) - blockIdx.x;
    int h = blockIdx.y, b = blockIdx.z;
    int q0 = qt * 128;
    int tid = threadIdx.x, lane = tid & 31, w = tid >> 5;
    int bh = b * NHh + h;

    const __half* qhb = qh + ((size_t)bh * Ss + q0) * QKD;
    const __half* khb = kh + (size_t)bh * Ss * QKD;
    const __half* vhb = vh + (size_t)bh * Ss * VDIM;

#pragma unroll
    for (int i = 0; i < 12; i++) {
        int e = tid + i * 256;
        int r = e / 24, c = e % 24;
        CP_ASYNC16(sb + r * FQ_PITCH + c * 16, qhb + (size_t)r * QKD + c * 8);
    }

    auto load_kv = [&](int kt, int s) {
        int k0 = kt * 32;
        uint32_t kst = sb + F_OFF_K + s * FK_SZ;
        uint32_t vst = sb + F_OFF_V + s * FV_SZ;
#pragma unroll
        for (int i = 0; i < 3; i++) {
            int e = tid + i * 256;
            int r = e / 24, c = e % 24;
            CP_ASYNC16(kst + r * FQ_PITCH + c * 16, khb + (size_t)(k0 + r) * QKD + c * 8);
        }
        {
            int e = tid * 2;
            int r = e >> 4, c = e & 15;
            CP_ASYNC16(vst + r * FV_PITCH + c * 16, vhb + (size_t)(k0 + r) * VDIM + c * 8);
            CP_ASYNC16(vst + r * FV_PITCH + (c + 1) * 16, vhb + (size_t)(k0 + r) * VDIM + (c + 1) * 8);
        }
    };

    load_kv(0, 0);
    CP_COMMIT();

    int a_r = w * 16 + (lane & 15);
    int a_c8 = (lane >> 4) << 3;
    int b_r = ((lane >> 4) << 3) + (lane & 7);
    int b_c8 = ((lane >> 3) & 1) << 3;
    int vt_r = lane & 15;
    int vt_c8 = (lane >> 4) << 3;

    int g = lane >> 2, t4 = lane & 3;

    float m0 = -INFINITY, m1 = -INFINITY, l0 = 0.f, l1 = 0.f;
    float O[16][4];
#pragma unroll
    for (int j = 0; j < 16; j++)
#pragma unroll
        for (int k = 0; k < 4; k++) O[j][k] = 0.f;

    int qrow0 = q0 + w * 16 + g;
    int qrow1 = qrow0 + 8;

    int nkt = (q0 + 128) >> 5;

    for (int kt = 0; kt < nkt; kt++) {
        int s = kt & 1;
        if (kt + 1 < nkt) { load_kv(kt + 1, s ^ 1); CP_COMMIT(); CP_WAIT1(); }
        else              { CP_WAIT0(); }
        __syncthreads();

        uint32_t kst = sb + F_OFF_K + s * FK_SZ;
        uint32_t vst = sb + F_OFF_V + s * FV_SZ;
        int k0 = kt * 32;

        float sc[4][4];
#pragma unroll
        for (int j = 0; j < 4; j++)
#pragma unroll
            for (int k = 0; k < 4; k++) sc[j][k] = 0.f;

#pragma unroll
        for (int kk = 0; kk < 12; kk++) {
            uint32_t ah[4];
            LDSM4(ah, sb + (uint32_t)(a_r * FQ_PITCH + (kk * 16 + a_c8) * 2));
#pragma unroll
            for (int nb = 0; nb < 2; nb++) {
                uint32_t bhf[4];
                LDSM4(bhf, kst + (uint32_t)((nb * 16 + b_r) * FQ_PITCH + (kk * 16 + b_c8) * 2));
                MMA16816(sc[2*nb],   ah, bhf[0], bhf[1]);
                MMA16816(sc[2*nb+1], ah, bhf[2], bhf[3]);
            }
        }

        if (k0 + 31 > q0) {
#pragma unroll
            for (int j = 0; j < 4; j++) {
                int col = k0 + j * 8 + t4 * 2;
                if (col     > qrow0) sc[j][0] = -INFINITY;
                if (col + 1 > qrow0) sc[j][1] = -INFINITY;
                if (col     > qrow1) sc[j][2] = -INFINITY;
                if (col + 1 > qrow1) sc[j][3] = -INFINITY;
            }
        }

        float rm0 = -INFINITY, rm1 = -INFINITY;
#pragma unroll
        for (int j = 0; j < 4; j++) {
            rm0 = fmaxf(rm0, fmaxf(sc[j][0], sc[j][1]));
            rm1 = fmaxf(rm1, fmaxf(sc[j][2], sc[j][3]));
        }
        rm0 = fmaxf(rm0, __shfl_xor_sync(0xffffffffu, rm0, 1));
        rm0 = fmaxf(rm0, __shfl_xor_sync(0xffffffffu, rm0, 2));
        rm1 = fmaxf(rm1, __shfl_xor_sync(0xffffffffu, rm1, 1));
        rm1 = fmaxf(rm1, __shfl_xor_sync(0xffffffffu, rm1, 2));
        float nm0 = fmaxf(m0, rm0), nm1 = fmaxf(m1, rm1);
        float rs0 = 0.f, rs1 = 0.f;
#pragma unroll
        for (int j = 0; j < 4; j++) {
            sc[j][0] = __expf(sc[j][0] - nm0);
            sc[j][1] = __expf(sc[j][1] - nm0);
            sc[j][2] = __expf(sc[j][2] - nm1);
            sc[j][3] = __expf(sc[j][3] - nm1);
            rs0 += sc[j][0] + sc[j][1];
            rs1 += sc[j][2] + sc[j][3];
        }
        rs0 += __shfl_xor_sync(0xffffffffu, rs0, 1);
        rs0 += __shfl_xor_sync(0xffffffffu, rs0, 2);
        rs1 += __shfl_xor_sync(0xffffffffu, rs1, 1);
        rs1 += __shfl_xor_sync(0xffffffffu, rs1, 2);
        float al0 = __expf(m0 - nm0), al1 = __expf(m1 - nm1);
        l0 = l0 * al0 + rs0; l1 = l1 * al1 + rs1;
        m0 = nm0; m1 = nm1;
#pragma unroll
        for (int j = 0; j < 16; j++) {
            O[j][0] *= al0; O[j][1] *= al0;
            O[j][2] *= al1; O[j][3] *= al1;
        }

        uint32_t ph2[4][2];
#pragma unroll
        for (int j = 0; j < 4; j++) {
            __half2 p01 = __floats2half2_rn(sc[j][0], sc[j][1]);
            __half2 p23 = __floats2half2_rn(sc[j][2], sc[j][3]);
            ph2[j][0] = *(uint32_t*)&p01;
            ph2[j][1] = *(uint32_t*)&p23;
        }

#pragma unroll
        for (int kk = 0; kk < 2; kk++) {
            uint32_t ah[4] = { ph2[2*kk][0], ph2[2*kk][1], ph2[2*kk+1][0], ph2[2*kk+1][1] };
#pragma unroll
            for (int j2 = 0; j2 < 8; j2++) {
                uint32_t vhf[4];
                LDSM4T(vhf, vst + (uint32_t)((kk * 16 + vt_r) * FV_PITCH + (j2 * 16 + vt_c8) * 2));
                MMA16816(O[2*j2],   ah, vhf[0], vhf[1]);
                MMA16816(O[2*j2+1], ah, vhf[2], vhf[3]);
            }
        }
        __syncthreads();
    }

    float inv0 = 1.f / l0, inv1 = 1.f / l1;
    size_t ob0 = ((size_t)(b * Ss + qrow0)) * (NHh * VDIM) + h * VDIM;
    size_t ob1 = ((size_t)(b * Ss + qrow1)) * (NHh * VDIM) + h * VDIM;
#pragma unroll
    for (int j = 0; j < 16; j++) {
        int d = j * 8 + t4 * 2;
        *(__half2*)(oh + ob0 + d) = __floats2half2_rn(O[j][0] * inv0, O[j][1] * inv0);
        *(__half2*)(oh + ob1 + d) = __floats2half2_rn(O[j][2] * inv1, O[j][3] * inv1);
    }
}

// ================= launch =================
extern "C" void kernel_launch(void* const* d_in, const int* in_sizes, int n_in,
                              void* d_out, int out_size) {
    const float* hs     = (const float*)d_in[0];
    const int*   pos    = (const int*)  d_in[1];
    const float* w_q_a  = (const float*)d_in[3];
    const float* q_ln   = (const float*)d_in[4];
    const float* w_q_b  = (const float*)d_in[5];
    const float* w_kv_a = (const float*)d_in[6];
    const float* kv_ln  = (const float*)d_in[7];
    const float* w_kv_b = (const float*)d_in[8];
    const float* w_o    = (const float*)d_in[9];
    float* out = (float*)d_out;

    float *qc, *kvt;
    cudaGetSymbolAddress((void**)&qc,  g_qc);
    cudaGetSymbolAddress((void**)&kvt, g_kvt);

    __half *hs_h,*qc_h,*kvc_h,*at_h;
    __half *wqa_h,*wqb_h,*wkva_h,*wkvb_h,*wo_h;
    __half *qfh,*kfh,*vfh;
    cudaGetSymbolAddress((void**)&hs_h,  g_hs_h);
    cudaGetSymbolAddress((void**)&qc_h,  g_qc_h);
    cudaGetSymbolAddress((void**)&kvc_h, g_kvc_h);
    cudaGetSymbolAddress((void**)&at_h,  g_at_h);
    cudaGetSymbolAddress((void**)&wqa_h, g_wqa_h);
    cudaGetSymbolAddress((void**)&wqb_h, g_wqb_h);
    cudaGetSymbolAddress((void**)&wkva_h,g_wkva_h);
    cudaGetSymbolAddress((void**)&wkvb_h,g_wkvb_h);
    cudaGetSymbolAddress((void**)&wo_h,  g_wo_h);
    cudaGetSymbolAddress((void**)&qfh,   g_qfh);
    cudaGetSymbolAddress((void**)&kfh,   g_kfh);
    cudaGetSymbolAddress((void**)&vfh,   g_vfh);

    cudaFuncSetAttribute(gemm_a, cudaFuncAttributeMaxDynamicSharedMemorySize, GEMM_SMEM);
    cudaFuncSetAttribute(gemm_b, cudaFuncAttributeMaxDynamicSharedMemorySize, GEMM_SMEM);
    cudaFuncSetAttribute(gemm_c, cudaFuncAttributeMaxDynamicSharedMemorySize, GEMM_SMEM);
    cudaFuncSetAttribute(flash_mma, cudaFuncAttributeMaxDynamicSharedMemorySize, FLASH_SMEM);

    // fork: prep_aux (weights for gemm_b/gemm_c) runs on a side stream,
    // overlapping prep_main + gemm_a on stream 0; joined before gemm_b.
    cudaStream_t s2;
    cudaStreamCreateWithFlags(&s2, cudaStreamNonBlocking);
    cudaEvent_t evFork, evJoin;
    cudaEventCreateWithFlags(&evFork, cudaEventDisableTiming);
    cudaEventCreateWithFlags(&evJoin, cudaEventDisableTiming);

    cudaEventRecord(evFork, 0);
    cudaStreamWaitEvent(s2, evFork, 0);
    prep_aux<<<4608 + 2048 + 4096, 256, 0, s2>>>(w_q_b, wqb_h, w_kv_b, wkvb_h, w_o, wo_h);
    cudaEventRecord(evJoin, s2);

    // stream 0: prep for gemm_a, then the dependency chain
    prep_main<<<4096 + 3072 + 1280, 256>>>(hs, hs_h, w_q_a, wqa_h, w_kv_a, wkva_h);

    gemm_a<<<dim3(12 + WKVA_NPAD/128, ROWS/128), 256, GEMM_SMEM>>>(
        hs_h, wqa_h, wkva_h, qc, kvt);

    norm_fused<<<2*ROWS, 256>>>(qc, q_ln, kvt, kv_ln, pos, qc_h, kvc_h, kfh);

    cudaStreamWaitEvent(0, evJoin, 0);

    gemm_b<<<dim3(24 + 32, ROWS/128), 256, GEMM_SMEM>>>(
        qc_h, wqb_h, kvc_h, wkvb_h, pos, qfh, kfh, vfh);

    flash_mma<<<dim3(Ss/128, NHh, Bb), 256, FLASH_SMEM>>>(qfh, kfh, vfh, at_h);

    gemm_c<<<dim3(HID/128, ROWS/128), 256, GEMM_SMEM>>>(at_h, wo_h, out);

    cudaEventDestroy(evFork);
    cudaEventDestroy(evJoin);
    cudaStreamDestroy(s2);
}

// round 10
// speedup vs baseline: 2.7754x; 1.0201x over previous
#include <cuda_runtime.h>
#include <cuda_fp16.h>
#include <math.h>
#include <cstdint>

// ---------------- problem constants ----------------
#define Bb   2
#define Ss   2048
#define HID  2048
#define NHh  16
#define QLORA 1536
#define KVLORA 512
#define NOPE 128
#define ROPED 64
#define VDIM 128
#define QKD  192
#define ROWS (Bb*Ss)          // 4096
#define WKVA_NPAD 640
#define SCALEF 0.07216878364870322f
#define LN10K  9.210340371976184f

// ---------------- fp32 scratch ----------------
__device__ float g_qc   [(size_t)ROWS * QLORA];
__device__ float g_kvt  [(size_t)ROWS * (KVLORA+ROPED)];

// ---------------- fp16 activations ----------------
__device__ __half g_hs_h [(size_t)ROWS*HID];
__device__ __half g_qc_h [(size_t)ROWS*QLORA];
__device__ __half g_kvc_h[(size_t)ROWS*KVLORA];
__device__ __half g_at_h [(size_t)ROWS*NHh*VDIM];

// ---------------- fp16 transposed weights [N,K] ----------------
__device__ __half g_wqa_h [(size_t)QLORA*HID];
__device__ __half g_wqb_h [(size_t)(NHh*QKD)*QLORA];
__device__ __half g_wkva_h[(size_t)WKVA_NPAD*HID];
__device__ __half g_wkvb_h[(size_t)(NHh*(NOPE+VDIM))*KVLORA];
__device__ __half g_wo_h  [(size_t)HID*(NHh*VDIM)];

// ---------------- flash fp16 buffers, [b,h,s,d] ----------------
__device__ __half g_qfh[(size_t)ROWS*NHh*QKD];
__device__ __half g_kfh[(size_t)ROWS*NHh*QKD];
__device__ __half g_vfh[(size_t)ROWS*NHh*VDIM];

// ================= helpers =================
__device__ __forceinline__ uint32_t smem_u32(const void* p) {
    uint32_t a;
    asm("{ .reg .u64 t; cvta.to.shared.u64 t, %1; cvt.u32.u64 %0, t; }" : "=r"(a) : "l"(p));
    return a;
}

#define LDSM4(r, a) asm volatile( \
    "ldmatrix.sync.aligned.m8n8.x4.shared.b16 {%0,%1,%2,%3}, [%4];" \
    : "=r"((r)[0]),"=r"((r)[1]),"=r"((r)[2]),"=r"((r)[3]) : "r"(a))

#define LDSM4T(r, a) asm volatile( \
    "ldmatrix.sync.aligned.m8n8.x4.trans.shared.b16 {%0,%1,%2,%3}, [%4];" \
    : "=r"((r)[0]),"=r"((r)[1]),"=r"((r)[2]),"=r"((r)[3]) : "r"(a))

#define MMA16816(d, a, b0v, b1v) asm volatile( \
    "mma.sync.aligned.m16n8k16.row.col.f32.f16.f16.f32 " \
    "{%0,%1,%2,%3},{%4,%5,%6,%7},{%8,%9},{%0,%1,%2,%3};" \
    : "+f"((d)[0]),"+f"((d)[1]),"+f"((d)[2]),"+f"((d)[3]) \
    : "r"((a)[0]),"r"((a)[1]),"r"((a)[2]),"r"((a)[3]), "r"(b0v),"r"(b1v))

#define CP_ASYNC16(sa, ga) asm volatile( \
    "cp.async.cg.shared.global [%0], [%1], 16;" :: "r"(sa), "l"(ga))
#define CP_COMMIT() asm volatile("cp.async.commit_group;" ::: "memory")
#define CP_WAIT1()  asm volatile("cp.async.wait_group 1;" ::: "memory")
#define CP_WAIT0()  asm volatile("cp.async.wait_group 0;" ::: "memory")

// ================= fp16 HMMA GEMM mainloop (shared) =================
#define BK 32
#define PITCH 40
#define TILE_B (128*PITCH*2)          // 10240
#define STAGE_B (2*TILE_B)            // 20480
#define NSTAGE 3
#define GEMM_SMEM (NSTAGE*STAGE_B)    // 61440

__device__ __forceinline__ void gemm_mainloop(
    const __half* __restrict__ gA, const __half* __restrict__ gB, int K,
    uint32_t sbase, float acc[2][8][4],
    int tid, int lane, int warpM, int warpN) {

    auto issue_loads = [&](int c, int s) {
        int k0 = c * BK;
        uint32_t st = sbase + s * STAGE_B;
#pragma unroll
        for (int j = 0; j < 2; j++) {
            int seg = tid + j * 256;
            int r = seg >> 2, cc = seg & 3;
            CP_ASYNC16(st + r * (PITCH * 2) + cc * 16, gA + (size_t)r * K + k0 + cc * 8);
            CP_ASYNC16(st + TILE_B + r * (PITCH * 2) + cc * 16, gB + (size_t)r * K + k0 + cc * 8);
        }
        CP_COMMIT();
    };

#pragma unroll
    for (int i = 0; i < 2; i++)
#pragma unroll
        for (int j = 0; j < 8; j++)
#pragma unroll
            for (int k = 0; k < 4; k++) acc[i][j][k] = 0.f;

    int a_r = warpM * 32 + (lane & 15);
    int a_c8 = (lane >> 4) << 3;
    int b_r = warpN * 64 + ((lane >> 4) << 3) + (lane & 7);
    int b_c8 = ((lane >> 3) & 1) << 3;

    auto compute = [&](int s) {
        uint32_t st = sbase + s * STAGE_B;
#pragma unroll
        for (int ki = 0; ki < 2; ki++) {
            uint32_t ah[2][4];
#pragma unroll
            for (int mi = 0; mi < 2; mi++) {
                uint32_t off = (uint32_t)((a_r + mi * 16) * (PITCH * 2) + (ki * 16 + a_c8) * 2);
                LDSM4(ah[mi], st + off);
            }
            uint32_t bh[4][4];
#pragma unroll
            for (int nb = 0; nb < 4; nb++) {
                uint32_t off = (uint32_t)((b_r + nb * 16) * (PITCH * 2) + (ki * 16 + b_c8) * 2);
                LDSM4(bh[nb], st + TILE_B + off);
            }
#pragma unroll
            for (int mi = 0; mi < 2; mi++)
#pragma unroll
                for (int nb = 0; nb < 4; nb++) {
                    MMA16816(acc[mi][2*nb],   ah[mi], bh[nb][0], bh[nb][1]);
                    MMA16816(acc[mi][2*nb+1], ah[mi], bh[nb][2], bh[nb][3]);
                }
        }
    };

    int nc = K / BK;
    issue_loads(0, 0);
    issue_loads(1, 1);
    for (int c = 0; c < nc; c++) {
        int s = c % NSTAGE;
        if (c + 1 < nc) { CP_WAIT1(); } else { CP_WAIT0(); }
        __syncthreads();
        if (c + 2 < nc) issue_loads(c + 2, (c + 2) % NSTAGE);
        compute(s);
    }
}

// ================= merged G1+G3 =================
__global__ void __launch_bounds__(256, 2) gemm_a(
    const __half* __restrict__ hs, const __half* __restrict__ wqa,
    const __half* __restrict__ wkva,
    float* __restrict__ qc, float* __restrict__ kvt) {
    extern __shared__ char sm[];
    uint32_t sbase = smem_u32(sm);
    int tid = threadIdx.x, lane = tid & 31, wid = tid >> 5;
    int warpM = wid & 3, warpN = wid >> 2;
    int row0 = blockIdx.y * 128;
    int bx = blockIdx.x;

    const __half* B;
    float* C; int cN, col0, Nlim;
    if (bx < 12) { col0 = bx * 128;        B = wqa  + (size_t)col0 * HID; C = qc;  cN = QLORA; Nlim = QLORA; }
    else         { col0 = (bx - 12) * 128; B = wkva + (size_t)col0 * HID; C = kvt; cN = KVLORA+ROPED; Nlim = KVLORA+ROPED; }

    float acc[2][8][4];
    gemm_mainloop(hs + (size_t)row0 * HID, B, HID, sbase, acc, tid, lane, warpM, warpN);

    int g = lane >> 2, t = lane & 3;
#pragma unroll
    for (int mi = 0; mi < 2; mi++)
#pragma unroll
        for (int n8 = 0; n8 < 8; n8++) {
            int col = col0 + warpN * 64 + n8 * 8 + t * 2;
            if (col < Nlim) {
                int r0 = row0 + warpM * 32 + mi * 16 + g;
                float* p0 = C + (size_t)r0 * cN + col;
                p0[0] = acc[mi][n8][0]; p0[1] = acc[mi][n8][1];
                float* p1 = p0 + (size_t)8 * cN;
                p1[0] = acc[mi][n8][2]; p1[1] = acc[mi][n8][3];
            }
        }
}

// ================= merged G2+G4 =================
__global__ void __launch_bounds__(256, 2) gemm_b(
    const __half* __restrict__ qch, const __half* __restrict__ wqb,
    const __half* __restrict__ kvch, const __half* __restrict__ wkvb,
    const int* __restrict__ pos,
    __half* __restrict__ qfh, __half* __restrict__ kfh, __half* __restrict__ vfh) {
    extern __shared__ char sm[];
    uint32_t sbase = smem_u32(sm);
    int tid = threadIdx.x, lane = tid & 31, wid = tid >> 5;
    int warpM = wid & 3, warpN = wid >> 2;
    int row0 = blockIdx.y * 128;
    int bx = blockIdx.x;
    int g = lane >> 2, t4 = lane & 3;

    if (bx < 24) {
        int col0 = bx * 128;
        float acc[2][8][4];
        gemm_mainloop(qch + (size_t)row0 * QLORA, wqb + (size_t)col0 * QLORA, QLORA,
                      sbase, acc, tid, lane, warpM, warpN);

        int colw = col0 + warpN * 64;
        int hH = colw / 192;
        int dbase = colw % 192;
        if (dbase != 128) {
#pragma unroll
            for (int mi = 0; mi < 2; mi++)
#pragma unroll
                for (int rr = 0; rr < 2; rr++) {
                    int row = row0 + warpM * 32 + mi * 16 + g + rr * 8;
                    int b = row >> 11, srow = row & 2047;
                    size_t obase = ((size_t)(b * NHh + hH) * Ss + srow) * QKD;
#pragma unroll
                    for (int n8 = 0; n8 < 8; n8++) {
                        int d = dbase + n8 * 8 + t4 * 2;
                        *(__half2*)(qfh + obase + d) = __floats2half2_rn(
                            acc[mi][n8][rr*2] * SCALEF, acc[mi][n8][rr*2+1] * SCALEF);
                    }
                }
        } else {
#pragma unroll
            for (int mi = 0; mi < 2; mi++)
#pragma unroll
                for (int rr = 0; rr < 2; rr++) {
                    int row = row0 + warpM * 32 + mi * 16 + g + rr * 8;
                    int b = row >> 11, srow = row & 2047;
                    float p = (float)pos[b * Ss + srow];
                    size_t obase = ((size_t)(b * NHh + hH) * Ss + srow) * QKD;
#pragma unroll
                    for (int n8 = 0; n8 < 4; n8++) {
                        int j0 = n8 * 8 + t4 * 2;
                        float if0 = __expf(-(float)j0 * (LN10K / 32.f));
                        float if1 = __expf(-(float)(j0 + 1) * (LN10K / 32.f));
                        float s0, c0, s1, c1;
                        __sincosf(p * if0, &s0, &c0);
                        __sincosf(p * if1, &s1, &c1);
                        float x1a = acc[mi][n8][rr*2],   x2a = acc[mi][n8+4][rr*2];
                        float x1b = acc[mi][n8][rr*2+1], x2b = acc[mi][n8+4][rr*2+1];
                        *(__half2*)(qfh + obase + 128 + j0) = __floats2half2_rn(
                            (x1a * c0 - x2a * s0) * SCALEF, (x1b * c1 - x2b * s1) * SCALEF);
                        *(__half2*)(qfh + obase + 160 + j0) = __floats2half2_rn(
                            (x2a * c0 + x1a * s0) * SCALEF, (x2b * c1 + x1b * s1) * SCALEF);
                    }
                }
        }
    } else {
        int col0 = (bx - 24) * 128;
        float acc[2][8][4];
        gemm_mainloop(kvch + (size_t)row0 * KVLORA, wkvb + (size_t)col0 * KVLORA, KVLORA,
                      sbase, acc, tid, lane, warpM, warpN);

        int hH = col0 >> 8;
        int isV = (col0 >> 7) & 1;
        __half* D = isV ? vfh : kfh;
        int stride = isV ? VDIM : QKD;
#pragma unroll
        for (int mi = 0; mi < 2; mi++)
#pragma unroll
            for (int n8 = 0; n8 < 8; n8++) {
                int col = col0 + warpN * 64 + n8 * 8 + t4 * 2;
                int d = col & 127;
#pragma unroll
                for (int rr = 0; rr < 2; rr++) {
                    int r0 = row0 + warpM * 32 + mi * 16 + g + rr * 8;
                    int b = r0 >> 11, srow = r0 & 2047;
                    size_t o = ((size_t)(b * NHh + hH) * Ss + srow) * stride + d;
                    *(__half2*)(D + o) = __floats2half2_rn(acc[mi][n8][rr*2], acc[mi][n8][rr*2+1]);
                }
            }
    }
}

// ================= G5 =================
__global__ void __launch_bounds__(256, 2) gemm_c(
    const __half* __restrict__ at, const __half* __restrict__ wo,
    float* __restrict__ out) {
    extern __shared__ char sm[];
    uint32_t sbase = smem_u32(sm);
    int tid = threadIdx.x, lane = tid & 31, wid = tid >> 5;
    int warpM = wid & 3, warpN = wid >> 2;
    int row0 = blockIdx.y * 128, col0 = blockIdx.x * 128;

    float acc[2][8][4];
    gemm_mainloop(at + (size_t)row0 * HID, wo + (size_t)col0 * HID, HID,
                  sbase, acc, tid, lane, warpM, warpN);

    int g = lane >> 2, t = lane & 3;
#pragma unroll
    for (int mi = 0; mi < 2; mi++)
#pragma unroll
        for (int n8 = 0; n8 < 8; n8++) {
            int col = col0 + warpN * 64 + n8 * 8 + t * 2;
            int r0 = row0 + warpM * 32 + mi * 16 + g;
            float* p0 = out + (size_t)r0 * HID + col;
            p0[0] = acc[mi][n8][0]; p0[1] = acc[mi][n8][1];
            float* p1 = p0 + (size_t)8 * HID;
            p1[0] = acc[mi][n8][2]; p1[1] = acc[mi][n8][3];
        }
}

// ================= merged prep kernels =================
__device__ __forceinline__ void do_transpose(
    const float* __restrict__ W, __half* __restrict__ Th,
    int K, int srcN, int colTiles, int tile, int tid) {
    __shared__ float t[32][33];
    int n0 = (tile % colTiles) * 32, k0 = (tile / colTiles) * 32;
    int tx = tid & 31, ty = tid >> 5;
#pragma unroll
    for (int i = 0; i < 4; i++) {
        int k = k0 + ty + i * 8, n = n0 + tx;
        t[ty + i * 8][tx] = (n < srcN) ? W[(size_t)k * srcN + n] : 0.f;
    }
    __syncthreads();
#pragma unroll
    for (int i = 0; i < 4; i++) {
        int n = n0 + ty + i * 8;
        Th[(size_t)n * K + k0 + tx] = __float2half(t[tx][ty + i * 8]);
    }
}

__global__ void prep_main(const float* __restrict__ hs, __half* __restrict__ hsh,
                          const float* __restrict__ wqa, __half* __restrict__ wqah,
                          const float* __restrict__ wkva, __half* __restrict__ wkvah) {
    int bx = blockIdx.x, tid = threadIdx.x;
    if (bx < 4096) {
        size_t i = ((size_t)bx * 256 + tid) * 8;
        float4 v0 = *(const float4*)(hs + i);
        float4 v1 = *(const float4*)(hs + i + 4);
        *(__half2*)(hsh + i)     = __floats2half2_rn(v0.x, v0.y);
        *(__half2*)(hsh + i + 2) = __floats2half2_rn(v0.z, v0.w);
        *(__half2*)(hsh + i + 4) = __floats2half2_rn(v1.x, v1.y);
        *(__half2*)(hsh + i + 6) = __floats2half2_rn(v1.z, v1.w);
    } else if (bx < 4096 + 3072) {
        do_transpose(wqa, wqah, HID, QLORA, QLORA/32, bx - 4096, tid);
    } else {
        do_transpose(wkva, wkvah, HID, KVLORA+ROPED, WKVA_NPAD/32, bx - 7168, tid);
    }
}

__global__ void prep_aux(const float* __restrict__ wqb, __half* __restrict__ wqbh,
                         const float* __restrict__ wkvb, __half* __restrict__ wkvbh,
                         const float* __restrict__ wo, __half* __restrict__ woh) {
    int bx = blockIdx.x, tid = threadIdx.x;
    if (bx < 4608) {
        do_transpose(wqb, wqbh, QLORA, NHh*QKD, (NHh*QKD)/32, bx, tid);
    } else if (bx < 4608 + 2048) {
        do_transpose(wkvb, wkvbh, KVLORA, NHh*(NOPE+VDIM), (NHh*(NOPE+VDIM))/32, bx - 4608, tid);
    } else {
        do_transpose(wo, woh, NHh*VDIM, HID, HID/32, bx - 6656, tid);
    }
}

// ================= register-resident single-pass norm =================
__device__ __forceinline__ float block_reduce_sum(float v, float* red8, int tid) {
    // warp reduce
#pragma unroll
    for (int off = 16; off > 0; off >>= 1)
        v += __shfl_xor_sync(0xffffffffu, v, off);
    if ((tid & 31) == 0) red8[tid >> 5] = v;
    __syncthreads();
    float s = (tid < 8) ? red8[tid] : 0.f;
#pragma unroll
    for (int off = 4; off > 0; off >>= 1)
        s += __shfl_xor_sync(0xffffffffu, s, off);
    if (tid == 0) red8[0] = s;
    __syncthreads();
    return red8[0];
}

__global__ void norm_fused(const float* __restrict__ qc, const float* __restrict__ qw,
                           const float* __restrict__ kvt, const float* __restrict__ kvw,
                           const int* __restrict__ pos,
                           __half* __restrict__ qch, __half* __restrict__ kvch,
                           __half* __restrict__ kfh) {
    __shared__ float red8[8];
    __shared__ float rop[64];
    int tid = threadIdx.x;
    if (blockIdx.x < ROWS) {
        int row = blockIdx.x;
        const float* r = qc + (size_t)row * QLORA;
        // load 6 floats/thread: float4 at 4*tid (0..1023), float2 at 1024+2*tid
        float4 v4 = *(const float4*)(r + 4 * tid);
        float2 v2 = *(const float2*)(r + 1024 + 2 * tid);
        float ss = v4.x*v4.x + v4.y*v4.y + v4.z*v4.z + v4.w*v4.w + v2.x*v2.x + v2.y*v2.y;
        float tot = block_reduce_sum(ss, red8, tid);
        float scale = rsqrtf(tot / (float)QLORA + 1e-6f);
        float4 w4 = *(const float4*)(qw + 4 * tid);
        float2 w2 = *(const float2*)(qw + 1024 + 2 * tid);
        __half* o = qch + (size_t)row * QLORA;
        *(__half2*)(o + 4*tid)        = __floats2half2_rn(v4.x*scale*w4.x, v4.y*scale*w4.y);
        *(__half2*)(o + 4*tid + 2)    = __floats2half2_rn(v4.z*scale*w4.z, v4.w*scale*w4.w);
        *(__half2*)(o + 1024 + 2*tid) = __floats2half2_rn(v2.x*scale*w2.x, v2.y*scale*w2.y);
    } else {
        int row = blockIdx.x - ROWS;
        const float* r = kvt + (size_t)row * (KVLORA + ROPED);
        float2 v2 = *(const float2*)(r + 2 * tid);
        float ss = v2.x*v2.x + v2.y*v2.y;
        // rope (independent of reduction) — compute early
        if (tid < 32) {
            float p = (float)pos[row];
            float inv_freq = __expf(-(float)tid * (LN10K / 32.f));
            float c, s;
            __sincosf(p * inv_freq, &s, &c);
            float x1 = r[KVLORA + tid];
            float x2 = r[KVLORA + 32 + tid];
            rop[tid]      = x1 * c - x2 * s;
            rop[tid + 32] = x2 * c + x1 * s;
        }
        float tot = block_reduce_sum(ss, red8, tid);
        float scale = rsqrtf(tot / (float)KVLORA + 1e-6f);
        float2 w2 = *(const float2*)(kvw + 2 * tid);
        *(__half2*)(kvch + (size_t)row * KVLORA + 2*tid) =
            __floats2half2_rn(v2.x*scale*w2.x, v2.y*scale*w2.y);
        int b = row >> 11, srow = row & 2047;
        for (int e = tid; e < NHh * ROPED; e += 256) {
            int h = e >> 6, d = e & 63;
            size_t o = ((size_t)(b * NHh + h) * Ss + srow) * QKD + NOPE + d;
            kfh[o] = __float2half(rop[d]);
        }
    }
}

// ================= fp16 tensor-core flash attention =================
#define FQ_PITCH 400
#define FV_PITCH 272
#define FQ_SZ    (128*FQ_PITCH)
#define FK_SZ    (32*FQ_PITCH)
#define FV_SZ    (32*FV_PITCH)
#define F_OFF_K  FQ_SZ
#define F_OFF_V  (F_OFF_K + 2*FK_SZ)
#define FLASH_SMEM (F_OFF_V + 2*FV_SZ)    // 94208

__global__ void __launch_bounds__(256, 2) flash_mma(
    const __half* __restrict__ qh, const __half* __restrict__ kh,
    const __half* __restrict__ vh, __half* __restrict__ oh) {
    extern __shared__ char sm[];
    uint32_t sb = smem_u32(sm);

    int qt = (gridDim.x - 1) - blockIdx.x;
    int h = blockIdx.y, b = blockIdx.z;
    int q0 = qt * 128;
    int tid = threadIdx.x, lane = tid & 31, w = tid >> 5;
    int bh = b * NHh + h;

    const __half* qhb = qh + ((size_t)bh * Ss + q0) * QKD;
    const __half* khb = kh + (size_t)bh * Ss * QKD;
    const __half* vhb = vh + (size_t)bh * Ss * VDIM;

#pragma unroll
    for (int i = 0; i < 12; i++) {
        int e = tid + i * 256;
        int r = e / 24, c = e % 24;
        CP_ASYNC16(sb + r * FQ_PITCH + c * 16, qhb + (size_t)r * QKD + c * 8);
    }

    auto load_kv = [&](int kt, int s) {
        int k0 = kt * 32;
        uint32_t kst = sb + F_OFF_K + s * FK_SZ;
        uint32_t vst = sb + F_OFF_V + s * FV_SZ;
#pragma unroll
        for (int i = 0; i < 3; i++) {
            int e = tid + i * 256;
            int r = e / 24, c = e % 24;
            CP_ASYNC16(kst + r * FQ_PITCH + c * 16, khb + (size_t)(k0 + r) * QKD + c * 8);
        }
        {
            int e = tid * 2;
            int r = e >> 4, c = e & 15;
            CP_ASYNC16(vst + r * FV_PITCH + c * 16, vhb + (size_t)(k0 + r) * VDIM + c * 8);
            CP_ASYNC16(vst + r * FV_PITCH + (c + 1) * 16, vhb + (size_t)(k0 + r) * VDIM + (c + 1) * 8);
        }
    };

    load_kv(0, 0);
    CP_COMMIT();

    int a_r = w * 16 + (lane & 15);
    int a_c8 = (lane >> 4) << 3;
    int b_r = ((lane >> 4) << 3) + (lane & 7);
    int b_c8 = ((lane >> 3) & 1) << 3;
    int vt_r = lane & 15;
    int vt_c8 = (lane >> 4) << 3;

    int g = lane >> 2, t4 = lane & 3;

    float m0 = -INFINITY, m1 = -INFINITY, l0 = 0.f, l1 = 0.f;
    float O[16][4];
#pragma unroll
    for (int j = 0; j < 16; j++)
#pragma unroll
        for (int k = 0; k < 4; k++) O[j][k] = 0.f;

    int qrow0 = q0 + w * 16 + g;
    int qrow1 = qrow0 + 8;

    int nkt = (q0 + 128) >> 5;

    for (int kt = 0; kt < nkt; kt++) {
        int s = kt & 1;
        if (kt + 1 < nkt) { load_kv(kt + 1, s ^ 1); CP_COMMIT(); CP_WAIT1(); }
        else              { CP_WAIT0(); }
        __syncthreads();

        uint32_t kst = sb + F_OFF_K + s * FK_SZ;
        uint32_t vst = sb + F_OFF_V + s * FV_SZ;
        int k0 = kt * 32;

        float sc[4][4];
#pragma unroll
        for (int j = 0; j < 4; j++)
#pragma unroll
            for (int k = 0; k < 4; k++) sc[j][k] = 0.f;

#pragma unroll
        for (int kk = 0; kk < 12; kk++) {
            uint32_t ah[4];
            LDSM4(ah, sb + (uint32_t)(a_r * FQ_PITCH + (kk * 16 + a_c8) * 2));
#pragma unroll
            for (int nb = 0; nb < 2; nb++) {
                uint32_t bhf[4];
                LDSM4(bhf, kst + (uint32_t)((nb * 16 + b_r) * FQ_PITCH + (kk * 16 + b_c8) * 2));
                MMA16816(sc[2*nb],   ah, bhf[0], bhf[1]);
                MMA16816(sc[2*nb+1], ah, bhf[2], bhf[3]);
            }
        }

        if (k0 + 31 > q0) {
#pragma unroll
            for (int j = 0; j < 4; j++) {
                int col = k0 + j * 8 + t4 * 2;
                if (col     > qrow0) sc[j][0] = -INFINITY;
                if (col + 1 > qrow0) sc[j][1] = -INFINITY;
                if (col     > qrow1) sc[j][2] = -INFINITY;
                if (col + 1 > qrow1) sc[j][3] = -INFINITY;
            }
        }

        float rm0 = -INFINITY, rm1 = -INFINITY;
#pragma unroll
        for (int j = 0; j < 4; j++) {
            rm0 = fmaxf(rm0, fmaxf(sc[j][0], sc[j][1]));
            rm1 = fmaxf(rm1, fmaxf(sc[j][2], sc[j][3]));
        }
        rm0 = fmaxf(rm0, __shfl_xor_sync(0xffffffffu, rm0, 1));
        rm0 = fmaxf(rm0, __shfl_xor_sync(0xffffffffu, rm0, 2));
        rm1 = fmaxf(rm1, __shfl_xor_sync(0xffffffffu, rm1, 1));
        rm1 = fmaxf(rm1, __shfl_xor_sync(0xffffffffu, rm1, 2));
        float nm0 = fmaxf(m0, rm0), nm1 = fmaxf(m1, rm1);
        float rs0 = 0.f, rs1 = 0.f;
#pragma unroll
        for (int j = 0; j < 4; j++) {
            sc[j][0] = __expf(sc[j][0] - nm0);
            sc[j][1] = __expf(sc[j][1] - nm0);
            sc[j][2] = __expf(sc[j][2] - nm1);
            sc[j][3] = __expf(sc[j][3] - nm1);
            rs0 += sc[j][0] + sc[j][1];
            rs1 += sc[j][2] + sc[j][3];
        }
        rs0 += __shfl_xor_sync(0xffffffffu, rs0, 1);
        rs0 += __shfl_xor_sync(0xffffffffu, rs0, 2);
        rs1 += __shfl_xor_sync(0xffffffffu, rs1, 1);
        rs1 += __shfl_xor_sync(0xffffffffu, rs1, 2);
        float al0 = __expf(m0 - nm0), al1 = __expf(m1 - nm1);
        l0 = l0 * al0 + rs0; l1 = l1 * al1 + rs1;
        m0 = nm0; m1 = nm1;
#pragma unroll
        for (int j = 0; j < 16; j++) {
            O[j][0] *= al0; O[j][1] *= al0;
            O[j][2] *= al1; O[j][3] *= al1;
        }

        uint32_t ph2[4][2];
#pragma unroll
        for (int j = 0; j < 4; j++) {
            __half2 p01 = __floats2half2_rn(sc[j][0], sc[j][1]);
            __half2 p23 = __floats2half2_rn(sc[j][2], sc[j][3]);
            ph2[j][0] = *(uint32_t*)&p01;
            ph2[j][1] = *(uint32_t*)&p23;
        }

#pragma unroll
        for (int kk = 0; kk < 2; kk++) {
            uint32_t ah[4] = { ph2[2*kk][0], ph2[2*kk][1], ph2[2*kk+1][0], ph2[2*kk+1][1] };
#pragma unroll
            for (int j2 = 0; j2 < 8; j2++) {
                uint32_t vhf[4];
                LDSM4T(vhf, vst + (uint32_t)((kk * 16 + vt_r) * FV_PITCH + (j2 * 16 + vt_c8) * 2));
                MMA16816(O[2*j2],   ah, vhf[0], vhf[1]);
                MMA16816(O[2*j2+1], ah, vhf[2], vhf[3]);
            }
        }
        __syncthreads();
    }

    float inv0 = 1.f / l0, inv1 = 1.f / l1;
    size_t ob0 = ((size_t)(b * Ss + qrow0)) * (NHh * VDIM) + h * VDIM;
    size_t ob1 = ((size_t)(b * Ss + qrow1)) * (NHh * VDIM) + h * VDIM;
#pragma unroll
    for (int j = 0; j < 16; j++) {
        int d = j * 8 + t4 * 2;
        *(__half2*)(oh + ob0 + d) = __floats2half2_rn(O[j][0] * inv0, O[j][1] * inv0);
        *(__half2*)(oh + ob1 + d) = __floats2half2_rn(O[j][2] * inv1, O[j][3] * inv1);
    }
}

// ================= launch =================
extern "C" void kernel_launch(void* const* d_in, const int* in_sizes, int n_in,
                              void* d_out, int out_size) {
    const float* hs     = (const float*)d_in[0];
    const int*   pos    = (const int*)  d_in[1];
    const float* w_q_a  = (const float*)d_in[3];
    const float* q_ln   = (const float*)d_in[4];
    const float* w_q_b  = (const float*)d_in[5];
    const float* w_kv_a = (const float*)d_in[6];
    const float* kv_ln  = (const float*)d_in[7];
    const float* w_kv_b = (const float*)d_in[8];
    const float* w_o    = (const float*)d_in[9];
    float* out = (float*)d_out;

    float *qc, *kvt;
    cudaGetSymbolAddress((void**)&qc,  g_qc);
    cudaGetSymbolAddress((void**)&kvt, g_kvt);

    __half *hs_h,*qc_h,*kvc_h,*at_h;
    __half *wqa_h,*wqb_h,*wkva_h,*wkvb_h,*wo_h;
    __half *qfh,*kfh,*vfh;
    cudaGetSymbolAddress((void**)&hs_h,  g_hs_h);
    cudaGetSymbolAddress((void**)&qc_h,  g_qc_h);
    cudaGetSymbolAddress((void**)&kvc_h, g_kvc_h);
    cudaGetSymbolAddress((void**)&at_h,  g_at_h);
    cudaGetSymbolAddress((void**)&wqa_h, g_wqa_h);
    cudaGetSymbolAddress((void**)&wqb_h, g_wqb_h);
    cudaGetSymbolAddress((void**)&wkva_h,g_wkva_h);
    cudaGetSymbolAddress((void**)&wkvb_h,g_wkvb_h);
    cudaGetSymbolAddress((void**)&wo_h,  g_wo_h);
    cudaGetSymbolAddress((void**)&qfh,   g_qfh);
    cudaGetSymbolAddress((void**)&kfh,   g_kfh);
    cudaGetSymbolAddress((void**)&vfh,   g_vfh);

    cudaFuncSetAttribute(gemm_a, cudaFuncAttributeMaxDynamicSharedMemorySize, GEMM_SMEM);
    cudaFuncSetAttribute(gemm_b, cudaFuncAttributeMaxDynamicSharedMemorySize, GEMM_SMEM);
    cudaFuncSetAttribute(gemm_c, cudaFuncAttributeMaxDynamicSharedMemorySize, GEMM_SMEM);
    cudaFuncSetAttribute(flash_mma, cudaFuncAttributeMaxDynamicSharedMemorySize, FLASH_SMEM);

    cudaStream_t s2;
    cudaStreamCreateWithFlags(&s2, cudaStreamNonBlocking);
    cudaEvent_t evFork, evJoin;
    cudaEventCreateWithFlags(&evFork, cudaEventDisableTiming);
    cudaEventCreateWithFlags(&evJoin, cudaEventDisableTiming);

    cudaEventRecord(evFork, 0);
    cudaStreamWaitEvent(s2, evFork, 0);
    prep_aux<<<4608 + 2048 + 4096, 256, 0, s2>>>(w_q_b, wqb_h, w_kv_b, wkvb_h, w_o, wo_h);
    cudaEventRecord(evJoin, s2);

    prep_main<<<4096 + 3072 + 1280, 256>>>(hs, hs_h, w_q_a, wqa_h, w_kv_a, wkva_h);

    gemm_a<<<dim3(12 + WKVA_NPAD/128, ROWS/128), 256, GEMM_SMEM>>>(
        hs_h, wqa_h, wkva_h, qc, kvt);

    norm_fused<<<2*ROWS, 256>>>(qc, q_ln, kvt, kv_ln, pos, qc_h, kvc_h, kfh);

    cudaStreamWaitEvent(0, evJoin, 0);

    gemm_b<<<dim3(24 + 32, ROWS/128), 256, GEMM_SMEM>>>(
        qc_h, wqb_h, kvc_h, wkvb_h, pos, qfh, kfh, vfh);

    flash_mma<<<dim3(Ss/128, NHh, Bb), 256, FLASH_SMEM>>>(qfh, kfh, vfh, at_h);

    gemm_c<<<dim3(HID/128, ROWS/128), 256, GEMM_SMEM>>>(at_h, wo_h, out);

    cudaEventDestroy(evFork);
    cudaEventDestroy(evJoin);
    cudaStreamDestroy(s2);
}